// round 2
// baseline (speedup 1.0000x reference)
#include <cuda_runtime.h>
#include <math.h>

// Problem constants: B=64, T=512, S=512, E=512, H=512
// out = [B,T,H] (16,777,216 f32) followed by h_last [1,B,H] (32,768 f32)

// ---------------- scratch (static device globals; no allocs) ----------------
__device__ float g_xi[64L * 512 * 1536];     // input projection [B*T, 3H]  (201 MB)
__device__ float g_dec[64L * 512 * 512];     // GRU outputs      [B*T, H]
__device__ float g_scores[64L * 512 * 512];  // scores / attn    [B, T, S]
__device__ float g_mix[64L * 512 * 512];     // attention mix    [B*T, H]
__device__ float g_out1[64L * 512 * 512];    // tanh(...)        [B*T, H]
__device__ float g_hbuf[2][64 * 512];        // double-buffered hidden state
__device__ unsigned g_bar[2];                // [0]=arrival counter (monotonic), [1]=generation

// ======================================================================
// Generic tiled SGEMM:  C[m,n] = act( sum_k A[m,k]*B'[k,n] + bias[n] )
//   TRANSB=true : B is [N,K] row-major (C = A * B^T)
//   TRANSB=false: B is [K,N] row-major (C = A * B)
// Concat support: for global k >= ksplit, A-element comes from A2 at col k-ksplit
// (both halves share lda). ACT: 0=none, 1=bias, 2=bias+tanh.
// BM=BN=128, BK=16, 256 threads, 8x8 per-thread tile. All dims divide tiles.
// ======================================================================
template <bool TRANSB, int ACT>
__global__ void __launch_bounds__(256) sgemm_k(
    const float* __restrict__ A, const float* __restrict__ A2, int ksplit, int lda,
    const float* __restrict__ Bm, int ldb,
    const float* __restrict__ bias,
    float* __restrict__ C, int ldc,
    int K, long sA, long sB, long sC)
{
    const int BM = 128, BN = 128, BK = 16;
    __shared__ float As[BK][BM];
    __shared__ float Bs[BK][BN];

    const int tid = threadIdx.x;
    const int m0 = blockIdx.y * BM;
    const int n0 = blockIdx.x * BN;
    const long zb = blockIdx.z;
    A  += zb * sA;
    A2 += zb * sA;
    Bm += zb * sB;
    C  += zb * sC;

    const int tx = tid & 15;   // n direction
    const int ty = tid >> 4;   // m direction

    float acc[8][8];
#pragma unroll
    for (int i = 0; i < 8; i++)
#pragma unroll
        for (int j = 0; j < 8; j++) acc[i][j] = 0.f;

    const int ntiles = K / BK;
    for (int kt = 0; kt < ntiles; ++kt) {
        const int kg0 = kt * BK;
        // ---- load A tile (transpose into As[k][m]) ----
#pragma unroll
        for (int l = 0; l < 2; l++) {
            int v = tid + l * 256;           // 512 float4s total
            int row = v >> 2;                // 0..127
            int kv = v & 3;                  // 0..3
            int kg = kg0 + kv * 4;
            const float* base = A;
            int kc = kg;
            if (kg >= ksplit) { base = A2; kc = kg - ksplit; }
            float4 x = *(const float4*)(base + (long)(m0 + row) * lda + kc);
            As[kv * 4 + 0][row] = x.x;
            As[kv * 4 + 1][row] = x.y;
            As[kv * 4 + 2][row] = x.z;
            As[kv * 4 + 3][row] = x.w;
        }
        // ---- load B tile ----
        if (TRANSB) {
#pragma unroll
            for (int l = 0; l < 2; l++) {
                int v = tid + l * 256;
                int row = v >> 2;            // n index 0..127
                int kv = v & 3;
                float4 x = *(const float4*)(Bm + (long)(n0 + row) * ldb + kg0 + kv * 4);
                Bs[kv * 4 + 0][row] = x.x;
                Bs[kv * 4 + 1][row] = x.y;
                Bs[kv * 4 + 2][row] = x.z;
                Bs[kv * 4 + 3][row] = x.w;
            }
        } else {
#pragma unroll
            for (int l = 0; l < 2; l++) {
                int v = tid + l * 256;
                int kr = v >> 5;             // 0..15
                int nc = (v & 31) * 4;       // 0..124
                float4 x = *(const float4*)(Bm + (long)(kg0 + kr) * ldb + n0 + nc);
                *(float4*)&Bs[kr][nc] = x;
            }
        }
        __syncthreads();

#pragma unroll
        for (int k = 0; k < BK; k++) {
            float am[8], bn[8];
            *(float4*)&am[0] = *(const float4*)&As[k][ty * 8];
            *(float4*)&am[4] = *(const float4*)&As[k][ty * 8 + 4];
            *(float4*)&bn[0] = *(const float4*)&Bs[k][tx * 8];
            *(float4*)&bn[4] = *(const float4*)&Bs[k][tx * 8 + 4];
#pragma unroll
            for (int i = 0; i < 8; i++)
#pragma unroll
                for (int j = 0; j < 8; j++) acc[i][j] = fmaf(am[i], bn[j], acc[i][j]);
        }
        __syncthreads();
    }

    // ---- epilogue ----
    float b8[8];
    if (ACT >= 1) {
#pragma unroll
        for (int j = 0; j < 8; j++) b8[j] = bias[n0 + tx * 8 + j];
    }
#pragma unroll
    for (int i = 0; i < 8; i++) {
        float* crow = C + (long)(m0 + ty * 8 + i) * ldc + n0 + tx * 8;
#pragma unroll
        for (int j = 0; j < 8; j += 4) {
            float4 o;
            float v0 = acc[i][j + 0], v1 = acc[i][j + 1], v2 = acc[i][j + 2], v3 = acc[i][j + 3];
            if (ACT >= 1) { v0 += b8[j]; v1 += b8[j + 1]; v2 += b8[j + 2]; v3 += b8[j + 3]; }
            if (ACT == 2) { v0 = tanhf(v0); v1 = tanhf(v1); v2 = tanhf(v2); v3 = tanhf(v3); }
            o.x = v0; o.y = v1; o.z = v2; o.w = v3;
            *(float4*)(crow + j) = o;
        }
    }
}

// ======================================================================
// Persistent GRU scan. 128 CTAs x 256 threads (1 CTA/SM, co-resident).
// CTA (bg,jg): bg in 0..3 (16 batches), jg in 0..31 (16 hidden units -> 48 W rows).
// Per step: C[16 x 48] = h[16 x 512] * Whh_slice^T, 8-warp K-split (64 k each),
// reduce in smem, gate math, write h_new (double-buffered) + dec_out.
// Grid-wide barrier: monotonic arrival counter + generation broadcast.
// ======================================================================
#define GRU_SMEM_FLOATS (48 * 516 + 16 * 516 + 8 * 768)
#define GRU_SMEM_BYTES (GRU_SMEM_FLOATS * 4)

__global__ void __launch_bounds__(256) gru_scan(const float* __restrict__ Whh,
                                                const float* __restrict__ bhh)
{
    extern __shared__ float sm[];
    float* Ws = sm;                         // [48][516]
    float* Hs = sm + 48 * 516;              // [16][516]
    float* Red = sm + 48 * 516 + 16 * 516;  // [8][768]

    const int tid = threadIdx.x;
    const int bg = blockIdx.x >> 5;   // 0..3
    const int jg = blockIdx.x & 31;   // 0..31
    const int b0 = bg * 16, j0 = jg * 16;

    // Load W slice: rowid = gate*16 + jl  -> global row gate*512 + j0 + jl
    for (int v = tid; v < 48 * 128; v += 256) {
        int rowid = v >> 7;
        int kc = (v & 127) << 2;
        int gate = rowid >> 4, jl = rowid & 15;
        float4 x = *(const float4*)(Whh + (long)(gate * 512 + j0 + jl) * 512 + kc);
        *(float4*)&Ws[rowid * 516 + kc] = x;
    }

    const int warp = tid >> 5, lane = tid & 31;
    const int bm = lane >> 3;   // 0..3
    const int jn = lane & 7;    // 0..7
    const int k0 = warp << 6;   // 64-wide k slice

    const int blc = tid >> 4, jlc = tid & 15;   // combine-phase mapping
    const float br = bhh[j0 + jlc];
    const float bz = bhh[512 + j0 + jlc];
    const float bnn = bhh[1024 + j0 + jlc];
    const int bglob = b0 + blc, jglob = j0 + jlc;

    for (int t = 0; t < 512; ++t) {
        const float* hcur = g_hbuf[t & 1];
        float* hnxt = g_hbuf[(t & 1) ^ 1];

        // stage h tile (bypass L1: written by other SMs)
        for (int v = tid; v < 2048; v += 256) {
            int r = v >> 7;
            int kc = (v & 127) << 2;
            float4 x = __ldcg((const float4*)(hcur + (b0 + r) * 512 + kc));
            *(float4*)&Hs[r * 516 + kc] = x;
        }
        __syncthreads();

        float acc[4][6];
#pragma unroll
        for (int i = 0; i < 4; i++)
#pragma unroll
            for (int g = 0; g < 6; g++) acc[i][g] = 0.f;

#pragma unroll 4
        for (int kk = 0; kk < 64; ++kk) {
            int k = k0 + kk;
            float hv[4], wv[6];
#pragma unroll
            for (int i = 0; i < 4; i++) hv[i] = Hs[(bm + 4 * i) * 516 + k];
#pragma unroll
            for (int g = 0; g < 6; g++) wv[g] = Ws[(jn + 8 * g) * 516 + k];
#pragma unroll
            for (int i = 0; i < 4; i++)
#pragma unroll
                for (int g = 0; g < 6; g++) acc[i][g] = fmaf(hv[i], wv[g], acc[i][g]);
        }
#pragma unroll
        for (int i = 0; i < 4; i++)
#pragma unroll
            for (int g = 0; g < 6; g++)
                Red[warp * 768 + (bm + 4 * i) * 48 + (jn + 8 * g)] = acc[i][g];
        __syncthreads();

        // combine: one (b,j) per thread
        float hr = br, hz = bz, hn = bnn;
#pragma unroll
        for (int w = 0; w < 8; ++w) {
            hr += Red[w * 768 + blc * 48 + jlc];
            hz += Red[w * 768 + blc * 48 + 16 + jlc];
            hn += Red[w * 768 + blc * 48 + 32 + jlc];
        }
        long xio = ((long)(bglob * 512 + t)) * 1536 + jglob;
        float xr = g_xi[xio];
        float xz = g_xi[xio + 512];
        float xn = g_xi[xio + 1024];
        float hold = Hs[blc * 516 + jglob];
        float r = 1.f / (1.f + expf(-(xr + hr)));
        float z = 1.f / (1.f + expf(-(xz + hz)));
        float n = tanhf(xn + r * hn);
        float hnew = (1.f - z) * n + z * hold;
        __stcg(&hnxt[bglob * 512 + jglob], hnew);
        g_dec[((long)(bglob * 512 + t)) * 512 + jglob] = hnew;

        // ---- grid-wide barrier (monotonic counter; no reset race) ----
        __syncthreads();
        if (tid == 0) {
            __threadfence();
            unsigned old = atomicAdd(&g_bar[0], 1u);
            unsigned want = (unsigned)t + 1u;
            if (old == (unsigned)t * 128u + 127u) {
                atomicExch(&g_bar[1], want);
            } else {
                while (*(volatile unsigned*)&g_bar[1] < want) { }
            }
            __threadfence();   // acquire + L1 invalidate (fence scope >= cluster)
        }
        __syncthreads();
    }
}

// ======================================================================
// Softmax over S=512 per (b,t) row, with encoder mask (True => -inf).
// ======================================================================
__global__ void __launch_bounds__(256) softmax_k(float* __restrict__ sc,
                                                 const unsigned char* __restrict__ mask)
{
    const int row = blockIdx.x;   // b*512 + t
    const int b = row >> 9;
    float* p = sc + (long)row * 512;
    const unsigned char* mp = mask + b * 512;
    const int tid = threadIdx.x;

    const float NEG_INF = -__int_as_float(0x7f800000);
    float v0 = p[tid], v1 = p[tid + 256];
    bool m0 = mp[tid] != 0, m1 = mp[tid + 256] != 0;
    if (m0) v0 = NEG_INF;
    if (m1) v1 = NEG_INF;

    __shared__ float red[8];
    __shared__ float bcast;

    float mx = fmaxf(v0, v1);
#pragma unroll
    for (int o = 16; o; o >>= 1) mx = fmaxf(mx, __shfl_xor_sync(0xffffffffu, mx, o));
    if ((tid & 31) == 0) red[tid >> 5] = mx;
    __syncthreads();
    if (tid < 8) {
        float x = red[tid];
#pragma unroll
        for (int o = 4; o; o >>= 1) x = fmaxf(x, __shfl_xor_sync(0xffu, x, o));
        if (tid == 0) bcast = x;
    }
    __syncthreads();
    mx = bcast;

    float e0 = m0 ? 0.f : __expf(v0 - mx);
    float e1 = m1 ? 0.f : __expf(v1 - mx);
    float s = e0 + e1;
#pragma unroll
    for (int o = 16; o; o >>= 1) s += __shfl_xor_sync(0xffffffffu, s, o);
    if ((tid & 31) == 0) red[tid >> 5] = s;
    __syncthreads();
    if (tid < 8) {
        float x = red[tid];
#pragma unroll
        for (int o = 4; o; o >>= 1) x += __shfl_xor_sync(0xffu, x, o);
        if (tid == 0) bcast = x;
    }
    __syncthreads();
    float inv = 1.f / bcast;
    p[tid] = e0 * inv;
    p[tid + 256] = e1 * inv;
}

__global__ void __launch_bounds__(256) copy_h_k(float* __restrict__ dst)
{
    int i = blockIdx.x * 256 + threadIdx.x;
    if (i < 64 * 512) dst[i] = g_hbuf[0][i];
}

// ======================================================================
// launch
// ======================================================================
extern "C" void kernel_launch(void* const* d_in, const int* in_sizes, int n_in,
                              void* d_out, int out_size)
{
    const float* X    = (const float*)d_in[0];   // [64,512,512]
    const float* Enc  = (const float*)d_in[1];   // [64,512,512]
    const unsigned char* Mask = (const unsigned char*)d_in[2];  // [64,512] bool
    const float* Wih  = (const float*)d_in[3];   // [1536,512]
    const float* Whh  = (const float*)d_in[4];   // [1536,512]
    const float* bih  = (const float*)d_in[5];   // [1536]
    const float* bhh  = (const float*)d_in[6];   // [1536]
    const float* Wao  = (const float*)d_in[7];   // [512,1024]
    const float* bao  = (const float*)d_in[8];   // [512]
    const float* Wd   = (const float*)d_in[9];   // [512,512]
    const float* bd   = (const float*)d_in[10];  // [512]
    float* out = (float*)d_out;

    void *p_xi, *p_dec, *p_sc, *p_mix, *p_o1, *p_h, *p_bar;
    cudaGetSymbolAddress(&p_xi, g_xi);
    cudaGetSymbolAddress(&p_dec, g_dec);
    cudaGetSymbolAddress(&p_sc, g_scores);
    cudaGetSymbolAddress(&p_mix, g_mix);
    cudaGetSymbolAddress(&p_o1, g_out1);
    cudaGetSymbolAddress(&p_h, g_hbuf);
    cudaGetSymbolAddress(&p_bar, g_bar);

    float* xi = (float*)p_xi;
    float* dec = (float*)p_dec;
    float* sc = (float*)p_sc;
    float* mix = (float*)p_mix;
    float* o1 = (float*)p_o1;

    cudaFuncSetAttribute(gru_scan, cudaFuncAttributeMaxDynamicSharedMemorySize, GRU_SMEM_BYTES);

    // h0 = 0 (buffer 0 is read at t=0) and barrier state = 0, every launch
    cudaMemsetAsync(p_h, 0, 64 * 512 * sizeof(float));
    cudaMemsetAsync(p_bar, 0, 2 * sizeof(unsigned));

    // 1) xi = X @ Wih^T + bih : [32768,1536]
    sgemm_k<true, 1><<<dim3(12, 256, 1), 256>>>(
        X, X, 512, 512, Wih, 512, bih, xi, 1536, 512, 0, 0, 0);

    // 2) GRU scan -> g_dec, h_last in g_hbuf[0]
    gru_scan<<<128, 256, GRU_SMEM_BYTES>>>(Whh, bhh);

    // 3) scores[b] = dec[b] @ enc[b]^T : 64 x [512,512]
    sgemm_k<true, 0><<<dim3(4, 4, 64), 256>>>(
        dec, dec, 512, 512, Enc, 512, nullptr, sc, 512, 512,
        262144L, 262144L, 262144L);

    // 4) softmax over S (with mask)
    softmax_k<<<64 * 512, 256>>>(sc, Mask);

    // 5) mix[b] = attn[b] @ enc[b] : 64 x [512,512]
    sgemm_k<false, 0><<<dim3(4, 4, 64), 256>>>(
        sc, sc, 512, 512, Enc, 512, nullptr, mix, 512, 512,
        262144L, 262144L, 262144L);

    // 6) out1 = tanh(concat(mix, dec) @ Wao^T + bao) : [32768,512], K=1024
    sgemm_k<true, 2><<<dim3(4, 256, 1), 256>>>(
        mix, dec, 512, 512, Wao, 1024, bao, o1, 512, 1024, 0, 0, 0);

    // 7) final = out1 @ Wd^T + bd -> d_out
    sgemm_k<true, 1><<<dim3(4, 256, 1), 256>>>(
        o1, o1, 512, 512, Wd, 512, bd, out, 512, 512, 0, 0, 0);

    // 8) h_last -> tail of d_out
    copy_h_k<<<128, 256>>>(out + (long)out_size - 64 * 512);
}

// round 4
// speedup vs baseline: 1.3077x; 1.3077x over previous
#include <cuda_runtime.h>
#include <cuda_bf16.h>
#include <math.h>
#include <stdint.h>

// Problem constants: B=64, T=512, S=512, E=512, H=512
// out = [B,T,H] (16,777,216 f32) followed by h_last [1,B,H] (32,768 f32)

// ---------------- scratch (static device globals; no allocs) ----------------
__device__ float g_xi[64L * 512 * 1536];     // input projection [B*T, 3H]
__device__ float g_dec[64L * 512 * 512];     // GRU outputs      [B*T, H]
__device__ float g_scores[64L * 512 * 512];  // scores / attn    [B, T, S]
__device__ float g_mix[64L * 512 * 512];     // attention mix    [B*T, H]
__device__ float g_out1[64L * 512 * 512];    // tanh(...)        [B*T, H]
__device__ float g_enct[64L * 512 * 512];    // Enc transposed   [B, H, S]
__device__ float g_hbuf[2][64 * 512];        // double-buffered hidden state
__device__ unsigned g_bar[2];                // [0]=arrival counter, [1]=generation

// ======================================================================
// bf16 HMMA (mma.sync m16n8k16) split-precision GEMM.
//   C[m,n] = act( sum_k A[m,k] * B[n,k] + bias[n] )    (B is [N,K] row-major)
// fp32 inputs are split per tile: x = hi(bf16) + lo(bf16 residual);
// C = Ah*Bh + Ah*Bl + Al*Bh  (~1e-5 rel err).
// Concat: for global k >= ksplit, A element comes from A2 at col k-ksplit.
// ACT: 0=none, 1=bias, 2=bias+tanh. Tile 128x128, K-chunk 32, 8 warps.
// ======================================================================
#define APAD 40  // row stride in bf16 (32 data + 8 pad) -> conflict-free frag loads

__device__ __forceinline__ void mma_bf16(float* c, const uint32_t* a,
                                         uint32_t b0, uint32_t b1) {
    asm volatile(
        "mma.sync.aligned.m16n8k16.row.col.f32.bf16.bf16.f32 "
        "{%0,%1,%2,%3}, {%4,%5,%6,%7}, {%8,%9}, {%0,%1,%2,%3};"
        : "+f"(c[0]), "+f"(c[1]), "+f"(c[2]), "+f"(c[3])
        : "r"(a[0]), "r"(a[1]), "r"(a[2]), "r"(a[3]), "r"(b0), "r"(b1));
}

__device__ __forceinline__ void cvt4(const float4 x, uint32_t& hi, uint32_t& hi2,
                                     uint32_t& lo, uint32_t& lo2) {
    __nv_bfloat162 h0 = __floats2bfloat162_rn(x.x, x.y);
    __nv_bfloat162 h1 = __floats2bfloat162_rn(x.z, x.w);
    __nv_bfloat162 l0 = __floats2bfloat162_rn(x.x - __bfloat162float(h0.x),
                                              x.y - __bfloat162float(h0.y));
    __nv_bfloat162 l1 = __floats2bfloat162_rn(x.z - __bfloat162float(h1.x),
                                              x.w - __bfloat162float(h1.y));
    hi = *reinterpret_cast<uint32_t*>(&h0);
    hi2 = *reinterpret_cast<uint32_t*>(&h1);
    lo = *reinterpret_cast<uint32_t*>(&l0);
    lo2 = *reinterpret_cast<uint32_t*>(&l1);
}

template <int ACT>
__global__ void __launch_bounds__(256) tgemm_k(
    const float* __restrict__ A, const float* __restrict__ A2, int ksplit, int lda,
    const float* __restrict__ Bm, int ldb,
    const float* __restrict__ bias,
    float* __restrict__ C, int ldc,
    int K, long sA, long sB, long sC)
{
    __shared__ __nv_bfloat16 As[2][128][APAD];  // [hi/lo][row][k]
    __shared__ __nv_bfloat16 Bs[2][128][APAD];

    const int tid = threadIdx.x, wid = tid >> 5, lane = tid & 31;
    const int m0 = blockIdx.y * 128, n0 = blockIdx.x * 128;
    const long zb = blockIdx.z;
    A += zb * sA; A2 += zb * sA; Bm += zb * sB; C += zb * sC;

    const int wm = wid & 3;        // 4 m-slices of 32
    const int wn = wid >> 2;       // 2 n-slices of 64
    const int lr = lane >> 2;      // 0..7
    const int lc = (lane & 3) * 2; // 0,2,4,6

    // loader mapping: each thread handles one row-half (16 fp32)
    const int ldr = tid >> 1;            // row 0..127
    const int ldc0 = (tid & 1) * 16;     // col 0 or 16

    float acc[2][8][4];
#pragma unroll
    for (int mi = 0; mi < 2; mi++)
#pragma unroll
        for (int ni = 0; ni < 8; ni++)
#pragma unroll
            for (int q = 0; q < 4; q++) acc[mi][ni][q] = 0.f;

    const int nchunks = K >> 5;
    for (int ch = 0; ch < nchunks; ++ch) {
        const int kg0 = ch << 5;
        const float* Ab = A;
        int kc = kg0;
        if (kg0 >= ksplit) { Ab = A2; kc = kg0 - ksplit; }

        // ---- load + convert A tile ----
        {
            const float* s = Ab + (long)(m0 + ldr) * lda + kc + ldc0;
#pragma unroll
            for (int i = 0; i < 4; i++) {
                float4 x = *(const float4*)(s + i * 4);
                uint32_t h0, h1, l0, l1;
                cvt4(x, h0, h1, l0, l1);
                int c = ldc0 + i * 4;
                *(uint2*)&As[0][ldr][c] = make_uint2(h0, h1);
                *(uint2*)&As[1][ldr][c] = make_uint2(l0, l1);
            }
        }
        // ---- load + convert B tile ----
        {
            const float* s = Bm + (long)(n0 + ldr) * ldb + kg0 + ldc0;
#pragma unroll
            for (int i = 0; i < 4; i++) {
                float4 x = *(const float4*)(s + i * 4);
                uint32_t h0, h1, l0, l1;
                cvt4(x, h0, h1, l0, l1);
                int c = ldc0 + i * 4;
                *(uint2*)&Bs[0][ldr][c] = make_uint2(h0, h1);
                *(uint2*)&Bs[1][ldr][c] = make_uint2(l0, l1);
            }
        }
        __syncthreads();

#pragma unroll
        for (int ks = 0; ks < 2; ++ks) {
            const int k0 = ks * 16;
            // A fragments (hi & lo) for both 16-row m-frags
            uint32_t afr[2][2][4];  // [hi/lo][mi][reg]
#pragma unroll
            for (int h = 0; h < 2; h++)
#pragma unroll
                for (int mi = 0; mi < 2; mi++) {
                    int r = wm * 32 + mi * 16 + lr;
                    afr[h][mi][0] = *(const uint32_t*)&As[h][r][k0 + lc];
                    afr[h][mi][1] = *(const uint32_t*)&As[h][r + 8][k0 + lc];
                    afr[h][mi][2] = *(const uint32_t*)&As[h][r][k0 + lc + 8];
                    afr[h][mi][3] = *(const uint32_t*)&As[h][r + 8][k0 + lc + 8];
                }
#pragma unroll
            for (int ni = 0; ni < 8; ni++) {
                int n = wn * 64 + ni * 8 + lr;
                uint32_t bh0 = *(const uint32_t*)&Bs[0][n][k0 + lc];
                uint32_t bh1 = *(const uint32_t*)&Bs[0][n][k0 + lc + 8];
                uint32_t bl0 = *(const uint32_t*)&Bs[1][n][k0 + lc];
                uint32_t bl1 = *(const uint32_t*)&Bs[1][n][k0 + lc + 8];
#pragma unroll
                for (int mi = 0; mi < 2; mi++) {
                    mma_bf16(acc[mi][ni], afr[0][mi], bh0, bh1);  // Ah*Bh
                    mma_bf16(acc[mi][ni], afr[0][mi], bl0, bl1);  // Ah*Bl
                    mma_bf16(acc[mi][ni], afr[1][mi], bh0, bh1);  // Al*Bh
                }
            }
        }
        __syncthreads();
    }

    // ---- epilogue ----
    // c-frag mapping: c0,c1 at (row lr, col 2*(lane&3)+{0,1}); c2,c3 at row lr+8.
#pragma unroll
    for (int mi = 0; mi < 2; mi++) {
#pragma unroll
        for (int ni = 0; ni < 8; ni++) {
            int n = n0 + wn * 64 + ni * 8 + (lane & 3) * 2;
            float b0 = 0.f, b1 = 0.f;
            if (ACT >= 1) { b0 = bias[n]; b1 = bias[n + 1]; }
#pragma unroll
            for (int half = 0; half < 2; half++) {
                int m = m0 + wm * 32 + mi * 16 + lr + half * 8;
                float v0 = acc[mi][ni][half * 2 + 0] + b0;
                float v1 = acc[mi][ni][half * 2 + 1] + b1;
                if (ACT == 0) { v0 = acc[mi][ni][half * 2 + 0]; v1 = acc[mi][ni][half * 2 + 1]; }
                if (ACT == 2) { v0 = tanhf(v0); v1 = tanhf(v1); }
                *(float2*)(C + (long)m * ldc + n) = make_float2(v0, v1);
            }
        }
    }
}

// ======================================================================
// Transpose Enc [B,S,H] -> EncT [B,H,S] (fp32)
// ======================================================================
__global__ void __launch_bounds__(256) transp_k(const float* __restrict__ src,
                                                float* __restrict__ dst)
{
    __shared__ float t[32][33];
    const int b = blockIdx.z;
    const int s0 = blockIdx.y * 32, h0 = blockIdx.x * 32;
    const float* S = src + ((long)b << 18);
    float* D = dst + ((long)b << 18);
    const int x = threadIdx.x, y = threadIdx.y;
#pragma unroll
    for (int i = 0; i < 32; i += 8) t[y + i][x] = S[(long)(s0 + y + i) * 512 + h0 + x];
    __syncthreads();
#pragma unroll
    for (int i = 0; i < 32; i += 8) D[(long)(h0 + y + i) * 512 + s0 + x] = t[x][y + i];
}

// ======================================================================
// Persistent GRU scan (unchanged — known correct). 128 CTAs x 256 threads.
// ======================================================================
#define GRU_SMEM_FLOATS (48 * 516 + 16 * 516 + 8 * 768)
#define GRU_SMEM_BYTES (GRU_SMEM_FLOATS * 4)

__global__ void __launch_bounds__(256) gru_scan(const float* __restrict__ Whh,
                                                const float* __restrict__ bhh)
{
    extern __shared__ float sm[];
    float* Ws = sm;                         // [48][516]
    float* Hs = sm + 48 * 516;              // [16][516]
    float* Red = sm + 48 * 516 + 16 * 516;  // [8][768]

    const int tid = threadIdx.x;
    const int bg = blockIdx.x >> 5;
    const int jg = blockIdx.x & 31;
    const int b0 = bg * 16, j0 = jg * 16;

    for (int v = tid; v < 48 * 128; v += 256) {
        int rowid = v >> 7;
        int kc = (v & 127) << 2;
        int gate = rowid >> 4, jl = rowid & 15;
        float4 x = *(const float4*)(Whh + (long)(gate * 512 + j0 + jl) * 512 + kc);
        *(float4*)&Ws[rowid * 516 + kc] = x;
    }

    const int warp = tid >> 5, lane = tid & 31;
    const int bm = lane >> 3;
    const int jn = lane & 7;
    const int k0 = warp << 6;

    const int blc = tid >> 4, jlc = tid & 15;
    const float br = bhh[j0 + jlc];
    const float bz = bhh[512 + j0 + jlc];
    const float bnn = bhh[1024 + j0 + jlc];
    const int bglob = b0 + blc, jglob = j0 + jlc;

    for (int t = 0; t < 512; ++t) {
        const float* hcur = g_hbuf[t & 1];
        float* hnxt = g_hbuf[(t & 1) ^ 1];

        for (int v = tid; v < 2048; v += 256) {
            int r = v >> 7;
            int kc = (v & 127) << 2;
            float4 x = __ldcg((const float4*)(hcur + (b0 + r) * 512 + kc));
            *(float4*)&Hs[r * 516 + kc] = x;
        }
        __syncthreads();

        float acc[4][6];
#pragma unroll
        for (int i = 0; i < 4; i++)
#pragma unroll
            for (int g = 0; g < 6; g++) acc[i][g] = 0.f;

#pragma unroll 4
        for (int kk = 0; kk < 64; ++kk) {
            int k = k0 + kk;
            float hv[4], wv[6];
#pragma unroll
            for (int i = 0; i < 4; i++) hv[i] = Hs[(bm + 4 * i) * 516 + k];
#pragma unroll
            for (int g = 0; g < 6; g++) wv[g] = Ws[(jn + 8 * g) * 516 + k];
#pragma unroll
            for (int i = 0; i < 4; i++)
#pragma unroll
                for (int g = 0; g < 6; g++) acc[i][g] = fmaf(hv[i], wv[g], acc[i][g]);
        }
#pragma unroll
        for (int i = 0; i < 4; i++)
#pragma unroll
            for (int g = 0; g < 6; g++)
                Red[warp * 768 + (bm + 4 * i) * 48 + (jn + 8 * g)] = acc[i][g];
        __syncthreads();

        float hr = br, hz = bz, hn = bnn;
#pragma unroll
        for (int w = 0; w < 8; ++w) {
            hr += Red[w * 768 + blc * 48 + jlc];
            hz += Red[w * 768 + blc * 48 + 16 + jlc];
            hn += Red[w * 768 + blc * 48 + 32 + jlc];
        }
        long xio = ((long)(bglob * 512 + t)) * 1536 + jglob;
        float xr = g_xi[xio];
        float xz = g_xi[xio + 512];
        float xn = g_xi[xio + 1024];
        float hold = Hs[blc * 516 + jglob];
        float r = 1.f / (1.f + expf(-(xr + hr)));
        float z = 1.f / (1.f + expf(-(xz + hz)));
        float n = tanhf(xn + r * hn);
        float hnew = (1.f - z) * n + z * hold;
        __stcg(&hnxt[bglob * 512 + jglob], hnew);
        g_dec[((long)(bglob * 512 + t)) * 512 + jglob] = hnew;

        __syncthreads();
        if (tid == 0) {
            __threadfence();
            unsigned old = atomicAdd(&g_bar[0], 1u);
            unsigned want = (unsigned)t + 1u;
            if (old == (unsigned)t * 128u + 127u) {
                atomicExch(&g_bar[1], want);
            } else {
                while (*(volatile unsigned*)&g_bar[1] < want) { }
            }
            __threadfence();
        }
        __syncthreads();
    }
}

// ======================================================================
// Softmax over S=512 per (b,t) row, with encoder mask (True => -inf).
// ======================================================================
__global__ void __launch_bounds__(256) softmax_k(float* __restrict__ sc,
                                                 const unsigned char* __restrict__ mask)
{
    const int row = blockIdx.x;
    const int b = row >> 9;
    float* p = sc + (long)row * 512;
    const unsigned char* mp = mask + b * 512;
    const int tid = threadIdx.x;

    const float NEG_INF = -__int_as_float(0x7f800000);
    float v0 = p[tid], v1 = p[tid + 256];
    bool m0 = mp[tid] != 0, m1 = mp[tid + 256] != 0;
    if (m0) v0 = NEG_INF;
    if (m1) v1 = NEG_INF;

    __shared__ float red[8];
    __shared__ float bcast;

    float mx = fmaxf(v0, v1);
#pragma unroll
    for (int o = 16; o; o >>= 1) mx = fmaxf(mx, __shfl_xor_sync(0xffffffffu, mx, o));
    if ((tid & 31) == 0) red[tid >> 5] = mx;
    __syncthreads();
    if (tid < 8) {
        float x = red[tid];
#pragma unroll
        for (int o = 4; o; o >>= 1) x = fmaxf(x, __shfl_xor_sync(0xffu, x, o));
        if (tid == 0) bcast = x;
    }
    __syncthreads();
    mx = bcast;

    float e0 = m0 ? 0.f : __expf(v0 - mx);
    float e1 = m1 ? 0.f : __expf(v1 - mx);
    float s = e0 + e1;
#pragma unroll
    for (int o = 16; o; o >>= 1) s += __shfl_xor_sync(0xffffffffu, s, o);
    if ((tid & 31) == 0) red[tid >> 5] = s;
    __syncthreads();
    if (tid < 8) {
        float x = red[tid];
#pragma unroll
        for (int o = 4; o; o >>= 1) x += __shfl_xor_sync(0xffu, x, o);
        if (tid == 0) bcast = x;
    }
    __syncthreads();
    float inv = 1.f / bcast;
    p[tid] = e0 * inv;
    p[tid + 256] = e1 * inv;
}

__global__ void __launch_bounds__(256) copy_h_k(float* __restrict__ dst)
{
    int i = blockIdx.x * 256 + threadIdx.x;
    if (i < 64 * 512) dst[i] = g_hbuf[0][i];
}

// ======================================================================
// launch
// ======================================================================
extern "C" void kernel_launch(void* const* d_in, const int* in_sizes, int n_in,
                              void* d_out, int out_size)
{
    const float* X    = (const float*)d_in[0];   // [64,512,512]
    const float* Enc  = (const float*)d_in[1];   // [64,512,512]
    const unsigned char* Mask = (const unsigned char*)d_in[2];  // [64,512] bool
    const float* Wih  = (const float*)d_in[3];   // [1536,512]
    const float* Whh  = (const float*)d_in[4];   // [1536,512]
    const float* bih  = (const float*)d_in[5];   // [1536]
    const float* bhh  = (const float*)d_in[6];   // [1536]
    const float* Wao  = (const float*)d_in[7];   // [512,1024]
    const float* bao  = (const float*)d_in[8];   // [512]
    const float* Wd   = (const float*)d_in[9];   // [512,512]
    const float* bd   = (const float*)d_in[10];  // [512]
    float* out = (float*)d_out;

    void *p_xi, *p_dec, *p_sc, *p_mix, *p_o1, *p_enct, *p_h, *p_bar;
    cudaGetSymbolAddress(&p_xi, g_xi);
    cudaGetSymbolAddress(&p_dec, g_dec);
    cudaGetSymbolAddress(&p_sc, g_scores);
    cudaGetSymbolAddress(&p_mix, g_mix);
    cudaGetSymbolAddress(&p_o1, g_out1);
    cudaGetSymbolAddress(&p_enct, g_enct);
    cudaGetSymbolAddress(&p_h, g_hbuf);
    cudaGetSymbolAddress(&p_bar, g_bar);

    float* xi = (float*)p_xi;
    float* dec = (float*)p_dec;
    float* sc = (float*)p_sc;
    float* mix = (float*)p_mix;
    float* o1 = (float*)p_o1;
    float* enct = (float*)p_enct;

    cudaFuncSetAttribute(gru_scan, cudaFuncAttributeMaxDynamicSharedMemorySize, GRU_SMEM_BYTES);

    cudaMemsetAsync(p_h, 0, 64 * 512 * sizeof(float));
    cudaMemsetAsync(p_bar, 0, 2 * sizeof(unsigned));

    const int KBIG = 1 << 30;

    // 0) EncT = transpose(Enc) per batch  [B,H,S]
    transp_k<<<dim3(16, 16, 64), dim3(32, 8)>>>(Enc, enct);

    // 1) xi = X @ Wih^T + bih : [32768,1536]
    tgemm_k<1><<<dim3(12, 256, 1), 256>>>(
        X, X, KBIG, 512, Wih, 512, bih, xi, 1536, 512, 0, 0, 0);

    // 2) GRU scan -> g_dec, h_last in g_hbuf[0]
    gru_scan<<<128, 256, GRU_SMEM_BYTES>>>(Whh, bhh);

    // 3) scores[b] = dec[b] @ enc[b]^T : 64 x [512,512]
    tgemm_k<0><<<dim3(4, 4, 64), 256>>>(
        dec, dec, KBIG, 512, Enc, 512, nullptr, sc, 512, 512,
        262144L, 262144L, 262144L);

    // 4) softmax over S (with mask)
    softmax_k<<<64 * 512, 256>>>(sc, Mask);

    // 5) mix[b] = attn[b] @ enc[b] = attn[b] @ encT[b]^T : 64 x [512,512]
    tgemm_k<0><<<dim3(4, 4, 64), 256>>>(
        sc, sc, KBIG, 512, enct, 512, nullptr, mix, 512, 512,
        262144L, 262144L, 262144L);

    // 6) out1 = tanh(concat(mix, dec) @ Wao^T + bao) : [32768,512], K=1024
    tgemm_k<2><<<dim3(4, 256, 1), 256>>>(
        mix, dec, 512, 512, Wao, 1024, bao, o1, 512, 1024, 0, 0, 0);

    // 7) final = out1 @ Wd^T + bd -> d_out
    tgemm_k<1><<<dim3(4, 256, 1), 256>>>(
        o1, o1, KBIG, 512, Wd, 512, bd, out, 512, 512, 0, 0, 0);

    // 8) h_last -> tail of d_out
    copy_h_k<<<128, 256>>>(out + (long)out_size - 64 * 512);
}

// round 5
// speedup vs baseline: 1.6519x; 1.2633x over previous
#include <cuda_runtime.h>
#include <cuda_bf16.h>
#include <math.h>
#include <stdint.h>

// Problem constants: B=64, T=512, S=512, E=512, H=512
// out = [B,T,H] (16,777,216 f32) followed by h_last [1,B,H] (32,768 f32)

// ---------------- scratch (static device globals; no allocs) ----------------
__device__ float g_xi[64L * 512 * 1536];     // input projection [B*T, 3H]
__device__ float g_dec[64L * 512 * 512];     // GRU outputs      [B*T, H]
__device__ float g_scores[64L * 512 * 512];  // scores / attn    [B, T, S]
__device__ float g_mix[64L * 512 * 512];     // attention mix    [B*T, H]
__device__ float g_out1[64L * 512 * 512];    // tanh(...)        [B*T, H]
__device__ float g_enct[64L * 512 * 512];    // Enc transposed   [B, H, S]
__device__ float g_hbuf[2][64 * 512];        // double-buffered hidden state
__device__ unsigned g_bar[2];                // [0]=arrival counter, [1]=generation

// ======================================================================
// Shared helpers: bf16 HMMA + fp32 -> bf16 hi/lo split conversion
// ======================================================================
__device__ __forceinline__ void mma_bf16(float* c, const uint32_t* a,
                                         uint32_t b0, uint32_t b1) {
    asm volatile(
        "mma.sync.aligned.m16n8k16.row.col.f32.bf16.bf16.f32 "
        "{%0,%1,%2,%3}, {%4,%5,%6,%7}, {%8,%9}, {%0,%1,%2,%3};"
        : "+f"(c[0]), "+f"(c[1]), "+f"(c[2]), "+f"(c[3])
        : "r"(a[0]), "r"(a[1]), "r"(a[2]), "r"(a[3]), "r"(b0), "r"(b1));
}

__device__ __forceinline__ void cvt4(const float4 x, uint32_t& hi, uint32_t& hi2,
                                     uint32_t& lo, uint32_t& lo2) {
    __nv_bfloat162 h0 = __floats2bfloat162_rn(x.x, x.y);
    __nv_bfloat162 h1 = __floats2bfloat162_rn(x.z, x.w);
    __nv_bfloat162 l0 = __floats2bfloat162_rn(x.x - __bfloat162float(h0.x),
                                              x.y - __bfloat162float(h0.y));
    __nv_bfloat162 l1 = __floats2bfloat162_rn(x.z - __bfloat162float(h1.x),
                                              x.w - __bfloat162float(h1.y));
    hi = *reinterpret_cast<uint32_t*>(&h0);
    hi2 = *reinterpret_cast<uint32_t*>(&h1);
    lo = *reinterpret_cast<uint32_t*>(&l0);
    lo2 = *reinterpret_cast<uint32_t*>(&l1);
}

// ======================================================================
// bf16 HMMA split-precision GEMM with register prefetch pipeline.
//   C[m,n] = act( sum_k A[m,k] * B[n,k] + bias[n] )    (B is [N,K] row-major)
// C = Ah*Bh + Ah*Bl + Al*Bh (~1e-5 rel err). Concat via A2/ksplit.
// ACT: 0=none, 1=bias, 2=bias+tanh. Tile 128x128, K-chunk 32, 8 warps.
// ======================================================================
#define APAD 40  // row stride in bf16 -> conflict-free frag loads

template <int ACT>
__global__ void __launch_bounds__(256, 2) tgemm_k(
    const float* __restrict__ A, const float* __restrict__ A2, int ksplit, int lda,
    const float* __restrict__ Bm, int ldb,
    const float* __restrict__ bias,
    float* __restrict__ C, int ldc,
    int K, long sA, long sB, long sC)
{
    __shared__ __nv_bfloat16 As[2][128][APAD];  // [hi/lo][row][k]
    __shared__ __nv_bfloat16 Bs[2][128][APAD];

    const int tid = threadIdx.x, wid = tid >> 5, lane = tid & 31;
    const int m0 = blockIdx.y * 128, n0 = blockIdx.x * 128;
    const long zb = blockIdx.z;
    A += zb * sA; A2 += zb * sA; Bm += zb * sB; C += zb * sC;

    const int wm = wid & 3;        // 4 m-slices of 32
    const int wn = wid >> 2;       // 2 n-slices of 64
    const int lr = lane >> 2;      // 0..7
    const int lc = (lane & 3) * 2; // 0,2,4,6

    const int ldr = tid >> 1;            // loader row 0..127
    const int ldc0 = (tid & 1) * 16;     // loader col 0 or 16

    float acc[2][8][4];
#pragma unroll
    for (int mi = 0; mi < 2; mi++)
#pragma unroll
        for (int ni = 0; ni < 8; ni++)
#pragma unroll
            for (int q = 0; q < 4; q++) acc[mi][ni][q] = 0.f;

    float4 pa[4], pb[4];
    // prologue: prefetch chunk 0 (kg0=0 is always < ksplit)
    {
        const float* sa = A + (long)(m0 + ldr) * lda + ldc0;
        const float* sb = Bm + (long)(n0 + ldr) * ldb + ldc0;
#pragma unroll
        for (int i = 0; i < 4; i++) {
            pa[i] = *(const float4*)(sa + i * 4);
            pb[i] = *(const float4*)(sb + i * 4);
        }
    }

    const int nchunks = K >> 5;
    for (int ch = 0; ch < nchunks; ++ch) {
        // ---- convert + store current chunk from prefetch regs ----
#pragma unroll
        for (int i = 0; i < 4; i++) {
            uint32_t h0, h1, l0, l1;
            int c = ldc0 + i * 4;
            cvt4(pa[i], h0, h1, l0, l1);
            *(uint2*)&As[0][ldr][c] = make_uint2(h0, h1);
            *(uint2*)&As[1][ldr][c] = make_uint2(l0, l1);
            cvt4(pb[i], h0, h1, l0, l1);
            *(uint2*)&Bs[0][ldr][c] = make_uint2(h0, h1);
            *(uint2*)&Bs[1][ldr][c] = make_uint2(l0, l1);
        }
        __syncthreads();

        // ---- prefetch next chunk (overlaps MMA below) ----
        if (ch + 1 < nchunks) {
            const int kg0 = (ch + 1) << 5;
            const float* Ab = A;
            int kc = kg0;
            if (kg0 >= ksplit) { Ab = A2; kc = kg0 - ksplit; }
            const float* sa = Ab + (long)(m0 + ldr) * lda + kc + ldc0;
            const float* sb = Bm + (long)(n0 + ldr) * ldb + kg0 + ldc0;
#pragma unroll
            for (int i = 0; i < 4; i++) {
                pa[i] = *(const float4*)(sa + i * 4);
                pb[i] = *(const float4*)(sb + i * 4);
            }
        }

        // ---- MMA on current chunk ----
#pragma unroll
        for (int ks = 0; ks < 2; ++ks) {
            const int k0 = ks * 16;
            uint32_t afr[2][2][4];  // [hi/lo][mi][reg]
#pragma unroll
            for (int h = 0; h < 2; h++)
#pragma unroll
                for (int mi = 0; mi < 2; mi++) {
                    int r = wm * 32 + mi * 16 + lr;
                    afr[h][mi][0] = *(const uint32_t*)&As[h][r][k0 + lc];
                    afr[h][mi][1] = *(const uint32_t*)&As[h][r + 8][k0 + lc];
                    afr[h][mi][2] = *(const uint32_t*)&As[h][r][k0 + lc + 8];
                    afr[h][mi][3] = *(const uint32_t*)&As[h][r + 8][k0 + lc + 8];
                }
#pragma unroll
            for (int ni = 0; ni < 8; ni++) {
                int n = wn * 64 + ni * 8 + lr;
                uint32_t bh0 = *(const uint32_t*)&Bs[0][n][k0 + lc];
                uint32_t bh1 = *(const uint32_t*)&Bs[0][n][k0 + lc + 8];
                uint32_t bl0 = *(const uint32_t*)&Bs[1][n][k0 + lc];
                uint32_t bl1 = *(const uint32_t*)&Bs[1][n][k0 + lc + 8];
#pragma unroll
                for (int mi = 0; mi < 2; mi++) {
                    mma_bf16(acc[mi][ni], afr[0][mi], bh0, bh1);
                    mma_bf16(acc[mi][ni], afr[0][mi], bl0, bl1);
                    mma_bf16(acc[mi][ni], afr[1][mi], bh0, bh1);
                }
            }
        }
        __syncthreads();
    }

    // ---- epilogue ----
#pragma unroll
    for (int mi = 0; mi < 2; mi++) {
#pragma unroll
        for (int ni = 0; ni < 8; ni++) {
            int n = n0 + wn * 64 + ni * 8 + (lane & 3) * 2;
            float b0 = 0.f, b1 = 0.f;
            if (ACT >= 1) { b0 = bias[n]; b1 = bias[n + 1]; }
#pragma unroll
            for (int half = 0; half < 2; half++) {
                int m = m0 + wm * 32 + mi * 16 + lr + half * 8;
                float v0 = acc[mi][ni][half * 2 + 0] + b0;
                float v1 = acc[mi][ni][half * 2 + 1] + b1;
                if (ACT == 0) { v0 = acc[mi][ni][half * 2 + 0]; v1 = acc[mi][ni][half * 2 + 1]; }
                if (ACT == 2) { v0 = tanhf(v0); v1 = tanhf(v1); }
                *(float2*)(C + (long)m * ldc + n) = make_float2(v0, v1);
            }
        }
    }
}

// ======================================================================
// Transpose Enc [B,S,H] -> EncT [B,H,S] (fp32)
// ======================================================================
__global__ void __launch_bounds__(256) transp_k(const float* __restrict__ src,
                                                float* __restrict__ dst)
{
    __shared__ float t[32][33];
    const int b = blockIdx.z;
    const int s0 = blockIdx.y * 32, h0 = blockIdx.x * 32;
    const float* S = src + ((long)b << 18);
    float* D = dst + ((long)b << 18);
    const int x = threadIdx.x, y = threadIdx.y;
#pragma unroll
    for (int i = 0; i < 32; i += 8) t[y + i][x] = S[(long)(s0 + y + i) * 512 + h0 + x];
    __syncthreads();
#pragma unroll
    for (int i = 0; i < 32; i += 8) D[(long)(h0 + y + i) * 512 + s0 + x] = t[x][y + i];
}

// ======================================================================
// Persistent tensor-core GRU scan. 128 CTAs x 256 threads (1/SM, co-resident).
// CTA (bg,jg): 16 batches x 16 hidden units (48 W rows). Per step:
// MMA C[16x48] = h[16x512](split bf16) * Whh_slice^T(split bf16, resident),
// 8-warp K-split (K=64 each), smem reduce, gate math, double-buffered h,
// monotonic grid barrier.
// ======================================================================
#define GRU_SMEM_BYTES ((2 * 48 * 520 + 2 * 16 * 520) * 2 + (8 * 800 + 16 * 16) * 4)

__global__ void __launch_bounds__(256) gru_scan(const float* __restrict__ Whh,
                                                const float* __restrict__ bhh)
{
    extern __shared__ char smg[];
    __nv_bfloat16* Wh = (__nv_bfloat16*)smg;              // [48][520]
    __nv_bfloat16* Wl = Wh + 48 * 520;
    __nv_bfloat16* Hh = Wl + 48 * 520;                    // [16][520]
    __nv_bfloat16* Hl = Hh + 16 * 520;
    float* Red = (float*)(Hl + 16 * 520);                 // [8][800] (row stride 50)
    float* Hf = Red + 8 * 800;                            // [16][16] fp32 h_old chunk

    const int tid = threadIdx.x;
    const int bg = blockIdx.x >> 5;   // 0..3
    const int jg = blockIdx.x & 31;   // 0..31
    const int b0 = bg * 16, j0 = jg * 16;

    // Load + split-convert W slice once (rows: gate*16+jl -> global gate*512+j0+jl)
    for (int v = tid; v < 48 * 128; v += 256) {
        int rowid = v >> 7, kc = (v & 127) << 2;
        int gate = rowid >> 4, jl = rowid & 15;
        float4 x = *(const float4*)(Whh + (long)(gate * 512 + j0 + jl) * 512 + kc);
        uint32_t h0, h1, l0, l1;
        cvt4(x, h0, h1, l0, l1);
        *(uint2*)&Wh[rowid * 520 + kc] = make_uint2(h0, h1);
        *(uint2*)&Wl[rowid * 520 + kc] = make_uint2(l0, l1);
    }

    const int warp = tid >> 5, lane = tid & 31;
    const int lr = lane >> 2, lc = (lane & 3) * 2;
    const int k0w = warp << 6;   // 64-wide K slice per warp

    const int blc = tid >> 4, jlc = tid & 15;   // combine-phase mapping
    const float br = bhh[j0 + jlc];
    const float bz = bhh[512 + j0 + jlc];
    const float bnn = bhh[1024 + j0 + jlc];
    const int bglob = b0 + blc, jglob = j0 + jlc;

    for (int t = 0; t < 512; ++t) {
        const float* hcur = g_hbuf[t & 1];
        float* hnxt = g_hbuf[(t & 1) ^ 1];

        // stage h tile: global fp32 -> smem bf16 hi/lo (+ fp32 stash of own cols)
        for (int v = tid; v < 2048; v += 256) {
            int r = v >> 7, kc = (v & 127) << 2;
            float4 x = __ldcg((const float4*)(hcur + (b0 + r) * 512 + kc));
            uint32_t h0, h1, l0, l1;
            cvt4(x, h0, h1, l0, l1);
            *(uint2*)&Hh[r * 520 + kc] = make_uint2(h0, h1);
            *(uint2*)&Hl[r * 520 + kc] = make_uint2(l0, l1);
            if ((kc >> 4) == jg) *(float4*)&Hf[r * 16 + (kc & 15)] = x;
        }
        __syncthreads();

        // MMA: M=16 (batch) x N=48 (gate rows) x K=64 (this warp's slice)
        float acc[6][4];
#pragma unroll
        for (int ni = 0; ni < 6; ni++)
#pragma unroll
            for (int q = 0; q < 4; q++) acc[ni][q] = 0.f;

#pragma unroll
        for (int ks = 0; ks < 4; ++ks) {
            const int k = k0w + ks * 16;
            uint32_t ah[4], al[4];
            ah[0] = *(const uint32_t*)&Hh[lr * 520 + k + lc];
            ah[1] = *(const uint32_t*)&Hh[(lr + 8) * 520 + k + lc];
            ah[2] = *(const uint32_t*)&Hh[lr * 520 + k + lc + 8];
            ah[3] = *(const uint32_t*)&Hh[(lr + 8) * 520 + k + lc + 8];
            al[0] = *(const uint32_t*)&Hl[lr * 520 + k + lc];
            al[1] = *(const uint32_t*)&Hl[(lr + 8) * 520 + k + lc];
            al[2] = *(const uint32_t*)&Hl[lr * 520 + k + lc + 8];
            al[3] = *(const uint32_t*)&Hl[(lr + 8) * 520 + k + lc + 8];
#pragma unroll
            for (int ni = 0; ni < 6; ++ni) {
                int n = ni * 8 + lr;
                uint32_t bh0 = *(const uint32_t*)&Wh[n * 520 + k + lc];
                uint32_t bh1 = *(const uint32_t*)&Wh[n * 520 + k + lc + 8];
                uint32_t bl0 = *(const uint32_t*)&Wl[n * 520 + k + lc];
                uint32_t bl1 = *(const uint32_t*)&Wl[n * 520 + k + lc + 8];
                mma_bf16(acc[ni], ah, bh0, bh1);
                mma_bf16(acc[ni], ah, bl0, bl1);
                mma_bf16(acc[ni], al, bh0, bh1);
            }
        }

        // write per-warp partials: Red[warp][m(16)][n(48)], row stride 50
        float* rw = Red + warp * 800;
#pragma unroll
        for (int ni = 0; ni < 6; ++ni) {
            int n = ni * 8 + (lane & 3) * 2;
            *(float2*)&rw[lr * 50 + n] = make_float2(acc[ni][0], acc[ni][1]);
            *(float2*)&rw[(lr + 8) * 50 + n] = make_float2(acc[ni][2], acc[ni][3]);
        }
        __syncthreads();

        // combine: one (b,j) per thread; reduce 8 warps' K-partials
        float hr = br, hz = bz, hn = bnn;
#pragma unroll
        for (int w = 0; w < 8; ++w) {
            hr += Red[w * 800 + blc * 50 + jlc];
            hz += Red[w * 800 + blc * 50 + 16 + jlc];
            hn += Red[w * 800 + blc * 50 + 32 + jlc];
        }
        long xio = ((long)(bglob * 512 + t)) * 1536 + jglob;
        float xr = g_xi[xio];
        float xz = g_xi[xio + 512];
        float xn = g_xi[xio + 1024];
        float hold = Hf[blc * 16 + jlc];
        float r = 1.f / (1.f + expf(-(xr + hr)));
        float z = 1.f / (1.f + expf(-(xz + hz)));
        float n = tanhf(xn + r * hn);
        float hnew = (1.f - z) * n + z * hold;
        __stcg(&hnxt[bglob * 512 + jglob], hnew);
        g_dec[((long)(bglob * 512 + t)) * 512 + jglob] = hnew;

        // ---- grid-wide barrier (monotonic counter; no reset race) ----
        __syncthreads();
        if (tid == 0) {
            __threadfence();
            unsigned old = atomicAdd(&g_bar[0], 1u);
            unsigned want = (unsigned)t + 1u;
            if (old == (unsigned)t * 128u + 127u) {
                atomicExch(&g_bar[1], want);
            } else {
                while (*(volatile unsigned*)&g_bar[1] < want) { }
            }
            __threadfence();
        }
        __syncthreads();
    }
}

// ======================================================================
// Softmax over S=512 per (b,t) row, with encoder mask (True => -inf).
// ======================================================================
__global__ void __launch_bounds__(256) softmax_k(float* __restrict__ sc,
                                                 const unsigned char* __restrict__ mask)
{
    const int row = blockIdx.x;
    const int b = row >> 9;
    float* p = sc + (long)row * 512;
    const unsigned char* mp = mask + b * 512;
    const int tid = threadIdx.x;

    const float NEG_INF = -__int_as_float(0x7f800000);
    float v0 = p[tid], v1 = p[tid + 256];
    bool m0 = mp[tid] != 0, m1 = mp[tid + 256] != 0;
    if (m0) v0 = NEG_INF;
    if (m1) v1 = NEG_INF;

    __shared__ float red[8];
    __shared__ float bcast;

    float mx = fmaxf(v0, v1);
#pragma unroll
    for (int o = 16; o; o >>= 1) mx = fmaxf(mx, __shfl_xor_sync(0xffffffffu, mx, o));
    if ((tid & 31) == 0) red[tid >> 5] = mx;
    __syncthreads();
    if (tid < 8) {
        float x = red[tid];
#pragma unroll
        for (int o = 4; o; o >>= 1) x = fmaxf(x, __shfl_xor_sync(0xffu, x, o));
        if (tid == 0) bcast = x;
    }
    __syncthreads();
    mx = bcast;

    float e0 = m0 ? 0.f : __expf(v0 - mx);
    float e1 = m1 ? 0.f : __expf(v1 - mx);
    float s = e0 + e1;
#pragma unroll
    for (int o = 16; o; o >>= 1) s += __shfl_xor_sync(0xffffffffu, s, o);
    if ((tid & 31) == 0) red[tid >> 5] = s;
    __syncthreads();
    if (tid < 8) {
        float x = red[tid];
#pragma unroll
        for (int o = 4; o; o >>= 1) x += __shfl_xor_sync(0xffu, x, o);
        if (tid == 0) bcast = x;
    }
    __syncthreads();
    float inv = 1.f / bcast;
    p[tid] = e0 * inv;
    p[tid + 256] = e1 * inv;
}

__global__ void __launch_bounds__(256) copy_h_k(float* __restrict__ dst)
{
    int i = blockIdx.x * 256 + threadIdx.x;
    if (i < 64 * 512) dst[i] = g_hbuf[0][i];
}

// ======================================================================
// launch
// ======================================================================
extern "C" void kernel_launch(void* const* d_in, const int* in_sizes, int n_in,
                              void* d_out, int out_size)
{
    const float* X    = (const float*)d_in[0];   // [64,512,512]
    const float* Enc  = (const float*)d_in[1];   // [64,512,512]
    const unsigned char* Mask = (const unsigned char*)d_in[2];  // [64,512] bool
    const float* Wih  = (const float*)d_in[3];   // [1536,512]
    const float* Whh  = (const float*)d_in[4];   // [1536,512]
    const float* bih  = (const float*)d_in[5];   // [1536]
    const float* bhh  = (const float*)d_in[6];   // [1536]
    const float* Wao  = (const float*)d_in[7];   // [512,1024]
    const float* bao  = (const float*)d_in[8];   // [512]
    const float* Wd   = (const float*)d_in[9];   // [512,512]
    const float* bd   = (const float*)d_in[10];  // [512]
    float* out = (float*)d_out;

    void *p_xi, *p_dec, *p_sc, *p_mix, *p_o1, *p_enct, *p_h, *p_bar;
    cudaGetSymbolAddress(&p_xi, g_xi);
    cudaGetSymbolAddress(&p_dec, g_dec);
    cudaGetSymbolAddress(&p_sc, g_scores);
    cudaGetSymbolAddress(&p_mix, g_mix);
    cudaGetSymbolAddress(&p_o1, g_out1);
    cudaGetSymbolAddress(&p_enct, g_enct);
    cudaGetSymbolAddress(&p_h, g_hbuf);
    cudaGetSymbolAddress(&p_bar, g_bar);

    float* xi = (float*)p_xi;
    float* dec = (float*)p_dec;
    float* sc = (float*)p_sc;
    float* mix = (float*)p_mix;
    float* o1 = (float*)p_o1;
    float* enct = (float*)p_enct;

    cudaFuncSetAttribute(gru_scan, cudaFuncAttributeMaxDynamicSharedMemorySize, GRU_SMEM_BYTES);

    cudaMemsetAsync(p_h, 0, 64 * 512 * sizeof(float));
    cudaMemsetAsync(p_bar, 0, 2 * sizeof(unsigned));

    const int KBIG = 1 << 30;

    // 0) EncT = transpose(Enc) per batch  [B,H,S]
    transp_k<<<dim3(16, 16, 64), dim3(32, 8)>>>(Enc, enct);

    // 1) xi = X @ Wih^T + bih : [32768,1536]
    tgemm_k<1><<<dim3(12, 256, 1), 256>>>(
        X, X, KBIG, 512, Wih, 512, bih, xi, 1536, 512, 0, 0, 0);

    // 2) GRU scan -> g_dec, h_last in g_hbuf[0]
    gru_scan<<<128, 256, GRU_SMEM_BYTES>>>(Whh, bhh);

    // 3) scores[b] = dec[b] @ enc[b]^T : 64 x [512,512]
    tgemm_k<0><<<dim3(4, 4, 64), 256>>>(
        dec, dec, KBIG, 512, Enc, 512, nullptr, sc, 512, 512,
        262144L, 262144L, 262144L);

    // 4) softmax over S (with mask)
    softmax_k<<<64 * 512, 256>>>(sc, Mask);

    // 5) mix[b] = attn[b] @ enc[b] = attn[b] @ encT[b]^T : 64 x [512,512]
    tgemm_k<0><<<dim3(4, 4, 64), 256>>>(
        sc, sc, KBIG, 512, enct, 512, nullptr, mix, 512, 512,
        262144L, 262144L, 262144L);

    // 6) out1 = tanh(concat(mix, dec) @ Wao^T + bao) : [32768,512], K=1024
    tgemm_k<2><<<dim3(4, 256, 1), 256>>>(
        mix, dec, 512, 512, Wao, 1024, bao, o1, 512, 1024, 0, 0, 0);

    // 7) final = out1 @ Wd^T + bd -> d_out
    tgemm_k<1><<<dim3(4, 256, 1), 256>>>(
        o1, o1, KBIG, 512, Wd, 512, bd, out, 512, 512, 0, 0, 0);

    // 8) h_last -> tail of d_out
    copy_h_k<<<128, 256>>>(out + (long)out_size - 64 * 512);
}

// round 6
// speedup vs baseline: 1.6812x; 1.0177x over previous
#include <cuda_runtime.h>
#include <cuda_bf16.h>
#include <math.h>
#include <stdint.h>

// Problem constants: B=64, T=512, S=512, E=512, H=512
// out = [B,T,H] (16,777,216 f32) followed by h_last [1,B,H] (32,768 f32)

// ---------------- scratch (static device globals; no allocs) ----------------
__device__ float g_xi[64L * 512 * 1536];     // input projection [B*T, 3H]
__device__ float g_dec[64L * 512 * 512];     // GRU outputs      [B*T, H]
__device__ float g_scores[64L * 512 * 512];  // scores / attn    [B, T, S]
__device__ float g_mix[64L * 512 * 512];     // attention mix    [B*T, H]
__device__ float g_out1[64L * 512 * 512];    // tanh(...)        [B*T, H]
__device__ float g_enct[64L * 512 * 512];    // Enc transposed   [B, H, S]
__device__ float g_hbuf[2][64 * 512];        // double-buffered hidden state
__device__ unsigned g_bar[2];                // [0]=arrival counter, [1]=generation

// ======================================================================
// Shared helpers: bf16 HMMA + fp32 -> bf16 hi/lo split conversion
// ======================================================================
__device__ __forceinline__ void mma_bf16(float* c, const uint32_t* a,
                                         uint32_t b0, uint32_t b1) {
    asm volatile(
        "mma.sync.aligned.m16n8k16.row.col.f32.bf16.bf16.f32 "
        "{%0,%1,%2,%3}, {%4,%5,%6,%7}, {%8,%9}, {%0,%1,%2,%3};"
        : "+f"(c[0]), "+f"(c[1]), "+f"(c[2]), "+f"(c[3])
        : "r"(a[0]), "r"(a[1]), "r"(a[2]), "r"(a[3]), "r"(b0), "r"(b1));
}

__device__ __forceinline__ void cvt4(const float4 x, uint32_t& hi, uint32_t& hi2,
                                     uint32_t& lo, uint32_t& lo2) {
    __nv_bfloat162 h0 = __floats2bfloat162_rn(x.x, x.y);
    __nv_bfloat162 h1 = __floats2bfloat162_rn(x.z, x.w);
    __nv_bfloat162 l0 = __floats2bfloat162_rn(x.x - __bfloat162float(h0.x),
                                              x.y - __bfloat162float(h0.y));
    __nv_bfloat162 l1 = __floats2bfloat162_rn(x.z - __bfloat162float(h1.x),
                                              x.w - __bfloat162float(h1.y));
    hi = *reinterpret_cast<uint32_t*>(&h0);
    hi2 = *reinterpret_cast<uint32_t*>(&h1);
    lo = *reinterpret_cast<uint32_t*>(&l0);
    lo2 = *reinterpret_cast<uint32_t*>(&l1);
}

// ======================================================================
// bf16 HMMA split-precision GEMM, register prefetch + 2-stage smem pipeline.
//   C[m,n] = act( sum_k A[m,k] * B[n,k] + bias[n] )    (B is [N,K] row-major)
// C = Ah*Bh + Ah*Bl + Al*Bh (~1e-5 rel err). Concat via A2/ksplit.
// ACT: 0=none, 1=bias, 2=bias+tanh. Tile 128x128, K-chunk 32, 8 warps.
// ======================================================================
#define APAD 40  // row stride in bf16 -> conflict-free frag loads
#define TG_TILE (128 * APAD)             // one [128][APAD] plane (bf16)
#define TG_SMEM_BYTES (2 * 2 * 2 * TG_TILE * 2)  // stages*(A,B)*(hi,lo)*plane*2B

template <int ACT>
__global__ void __launch_bounds__(256, 2) tgemm_k(
    const float* __restrict__ A, const float* __restrict__ A2, int ksplit, int lda,
    const float* __restrict__ Bm, int ldb,
    const float* __restrict__ bias,
    float* __restrict__ C, int ldc,
    int K, long sA, long sB, long sC)
{
    extern __shared__ __nv_bfloat16 smtg[];
    // layout: [stage][A:0/B:1][hi:0/lo:1][row][APAD]
    auto plane = [&](int st, int ab, int h) -> __nv_bfloat16* {
        return smtg + (((st * 2 + ab) * 2 + h) * TG_TILE);
    };

    const int tid = threadIdx.x, wid = tid >> 5, lane = tid & 31;
    const int m0 = blockIdx.y * 128, n0 = blockIdx.x * 128;
    const long zb = blockIdx.z;
    A += zb * sA; A2 += zb * sA; Bm += zb * sB; C += zb * sC;

    const int wm = wid & 3;        // 4 m-slices of 32
    const int wn = wid >> 2;       // 2 n-slices of 64
    const int lr = lane >> 2;      // 0..7
    const int lc = (lane & 3) * 2; // 0,2,4,6

    const int ldr = tid >> 1;            // loader row 0..127
    const int ldc0 = (tid & 1) * 16;     // loader col 0 or 16

    float acc[2][8][4];
#pragma unroll
    for (int mi = 0; mi < 2; mi++)
#pragma unroll
        for (int ni = 0; ni < 8; ni++)
#pragma unroll
            for (int q = 0; q < 4; q++) acc[mi][ni][q] = 0.f;

    float4 pa[4], pb[4];
    // prologue: prefetch chunk 0 (kg0=0 always < ksplit), stage into buffer 0
    {
        const float* sa = A + (long)(m0 + ldr) * lda + ldc0;
        const float* sb = Bm + (long)(n0 + ldr) * ldb + ldc0;
#pragma unroll
        for (int i = 0; i < 4; i++) {
            pa[i] = *(const float4*)(sa + i * 4);
            pb[i] = *(const float4*)(sb + i * 4);
        }
    }
    {
        __nv_bfloat16 *ah = plane(0, 0, 0), *al = plane(0, 0, 1);
        __nv_bfloat16 *bh = plane(0, 1, 0), *bl = plane(0, 1, 1);
#pragma unroll
        for (int i = 0; i < 4; i++) {
            uint32_t h0, h1, l0, l1;
            int c = ldc0 + i * 4;
            cvt4(pa[i], h0, h1, l0, l1);
            *(uint2*)&ah[ldr * APAD + c] = make_uint2(h0, h1);
            *(uint2*)&al[ldr * APAD + c] = make_uint2(l0, l1);
            cvt4(pb[i], h0, h1, l0, l1);
            *(uint2*)&bh[ldr * APAD + c] = make_uint2(h0, h1);
            *(uint2*)&bl[ldr * APAD + c] = make_uint2(l0, l1);
        }
    }
    __syncthreads();

    const int nchunks = K >> 5;
    for (int ch = 0; ch < nchunks; ++ch) {
        // ---- prefetch next chunk into registers (overlaps MMA below) ----
        const bool more = (ch + 1 < nchunks);
        if (more) {
            const int kg0 = (ch + 1) << 5;
            const float* Ab = A;
            int kc = kg0;
            if (kg0 >= ksplit) { Ab = A2; kc = kg0 - ksplit; }
            const float* sa = Ab + (long)(m0 + ldr) * lda + kc + ldc0;
            const float* sb = Bm + (long)(n0 + ldr) * ldb + kg0 + ldc0;
#pragma unroll
            for (int i = 0; i < 4; i++) {
                pa[i] = *(const float4*)(sa + i * 4);
                pb[i] = *(const float4*)(sb + i * 4);
            }
        }

        // ---- MMA on current stage ----
        const int st = ch & 1;
        const __nv_bfloat16* Ah = plane(st, 0, 0);
        const __nv_bfloat16* Al = plane(st, 0, 1);
        const __nv_bfloat16* Bh = plane(st, 1, 0);
        const __nv_bfloat16* Bl = plane(st, 1, 1);
#pragma unroll
        for (int ks = 0; ks < 2; ++ks) {
            const int k0 = ks * 16;
            uint32_t afr[2][2][4];  // [hi/lo][mi][reg]
#pragma unroll
            for (int mi = 0; mi < 2; mi++) {
                int r = wm * 32 + mi * 16 + lr;
                afr[0][mi][0] = *(const uint32_t*)&Ah[r * APAD + k0 + lc];
                afr[0][mi][1] = *(const uint32_t*)&Ah[(r + 8) * APAD + k0 + lc];
                afr[0][mi][2] = *(const uint32_t*)&Ah[r * APAD + k0 + lc + 8];
                afr[0][mi][3] = *(const uint32_t*)&Ah[(r + 8) * APAD + k0 + lc + 8];
                afr[1][mi][0] = *(const uint32_t*)&Al[r * APAD + k0 + lc];
                afr[1][mi][1] = *(const uint32_t*)&Al[(r + 8) * APAD + k0 + lc];
                afr[1][mi][2] = *(const uint32_t*)&Al[r * APAD + k0 + lc + 8];
                afr[1][mi][3] = *(const uint32_t*)&Al[(r + 8) * APAD + k0 + lc + 8];
            }
#pragma unroll
            for (int ni = 0; ni < 8; ni++) {
                int n = wn * 64 + ni * 8 + lr;
                uint32_t bh0 = *(const uint32_t*)&Bh[n * APAD + k0 + lc];
                uint32_t bh1 = *(const uint32_t*)&Bh[n * APAD + k0 + lc + 8];
                uint32_t bl0 = *(const uint32_t*)&Bl[n * APAD + k0 + lc];
                uint32_t bl1 = *(const uint32_t*)&Bl[n * APAD + k0 + lc + 8];
#pragma unroll
                for (int mi = 0; mi < 2; mi++) {
                    mma_bf16(acc[mi][ni], afr[0][mi], bh0, bh1);
                    mma_bf16(acc[mi][ni], afr[0][mi], bl0, bl1);
                    mma_bf16(acc[mi][ni], afr[1][mi], bh0, bh1);
                }
            }
        }

        // ---- convert + store next chunk into idle stage, then one sync ----
        if (more) {
            const int ns = st ^ 1;
            __nv_bfloat16 *ah = plane(ns, 0, 0), *al = plane(ns, 0, 1);
            __nv_bfloat16 *bh = plane(ns, 1, 0), *bl = plane(ns, 1, 1);
#pragma unroll
            for (int i = 0; i < 4; i++) {
                uint32_t h0, h1, l0, l1;
                int c = ldc0 + i * 4;
                cvt4(pa[i], h0, h1, l0, l1);
                *(uint2*)&ah[ldr * APAD + c] = make_uint2(h0, h1);
                *(uint2*)&al[ldr * APAD + c] = make_uint2(l0, l1);
                cvt4(pb[i], h0, h1, l0, l1);
                *(uint2*)&bh[ldr * APAD + c] = make_uint2(h0, h1);
                *(uint2*)&bl[ldr * APAD + c] = make_uint2(l0, l1);
            }
            __syncthreads();
        }
    }

    // ---- epilogue ----
#pragma unroll
    for (int mi = 0; mi < 2; mi++) {
#pragma unroll
        for (int ni = 0; ni < 8; ni++) {
            int n = n0 + wn * 64 + ni * 8 + (lane & 3) * 2;
            float b0 = 0.f, b1 = 0.f;
            if (ACT >= 1) { b0 = bias[n]; b1 = bias[n + 1]; }
#pragma unroll
            for (int half = 0; half < 2; half++) {
                int m = m0 + wm * 32 + mi * 16 + lr + half * 8;
                float v0 = acc[mi][ni][half * 2 + 0] + b0;
                float v1 = acc[mi][ni][half * 2 + 1] + b1;
                if (ACT == 0) { v0 = acc[mi][ni][half * 2 + 0]; v1 = acc[mi][ni][half * 2 + 1]; }
                if (ACT == 2) { v0 = tanhf(v0); v1 = tanhf(v1); }
                *(float2*)(C + (long)m * ldc + n) = make_float2(v0, v1);
            }
        }
    }
}

// ======================================================================
// Transpose Enc [B,S,H] -> EncT [B,H,S] (fp32)
// ======================================================================
__global__ void __launch_bounds__(256) transp_k(const float* __restrict__ src,
                                                float* __restrict__ dst)
{
    __shared__ float t[32][33];
    const int b = blockIdx.z;
    const int s0 = blockIdx.y * 32, h0 = blockIdx.x * 32;
    const float* S = src + ((long)b << 18);
    float* D = dst + ((long)b << 18);
    const int x = threadIdx.x, y = threadIdx.y;
#pragma unroll
    for (int i = 0; i < 32; i += 8) t[y + i][x] = S[(long)(s0 + y + i) * 512 + h0 + x];
    __syncthreads();
#pragma unroll
    for (int i = 0; i < 32; i += 8) D[(long)(h0 + y + i) * 512 + s0 + x] = t[x][y + i];
}

// ======================================================================
// Persistent tensor-core GRU scan. 128 CTAs x 256 threads (1/SM, co-resident).
// xi prefetched at step start (DRAM latency overlapped with h staging + MMA);
// g_dec store moved after fence+arrive (off tid0's fence drain path).
// ======================================================================
#define GRU_SMEM_BYTES ((2 * 48 * 520 + 2 * 16 * 520) * 2 + (8 * 800 + 16 * 16) * 4)

__global__ void __launch_bounds__(256) gru_scan(const float* __restrict__ Whh,
                                                const float* __restrict__ bhh)
{
    extern __shared__ char smg[];
    __nv_bfloat16* Wh = (__nv_bfloat16*)smg;              // [48][520]
    __nv_bfloat16* Wl = Wh + 48 * 520;
    __nv_bfloat16* Hh = Wl + 48 * 520;                    // [16][520]
    __nv_bfloat16* Hl = Hh + 16 * 520;
    float* Red = (float*)(Hl + 16 * 520);                 // [8][800] (row stride 50)
    float* Hf = Red + 8 * 800;                            // [16][16] fp32 h_old chunk

    const int tid = threadIdx.x;
    const int bg = blockIdx.x >> 5;   // 0..3
    const int jg = blockIdx.x & 31;   // 0..31
    const int b0 = bg * 16, j0 = jg * 16;

    // Load + split-convert W slice once
    for (int v = tid; v < 48 * 128; v += 256) {
        int rowid = v >> 7, kc = (v & 127) << 2;
        int gate = rowid >> 4, jl = rowid & 15;
        float4 x = *(const float4*)(Whh + (long)(gate * 512 + j0 + jl) * 512 + kc);
        uint32_t h0, h1, l0, l1;
        cvt4(x, h0, h1, l0, l1);
        *(uint2*)&Wh[rowid * 520 + kc] = make_uint2(h0, h1);
        *(uint2*)&Wl[rowid * 520 + kc] = make_uint2(l0, l1);
    }

    const int warp = tid >> 5, lane = tid & 31;
    const int lr = lane >> 2, lc = (lane & 3) * 2;
    const int k0w = warp << 6;   // 64-wide K slice per warp

    const int blc = tid >> 4, jlc = tid & 15;   // combine-phase mapping
    const float br = bhh[j0 + jlc];
    const float bz = bhh[512 + j0 + jlc];
    const float bnn = bhh[1024 + j0 + jlc];
    const int bglob = b0 + blc, jglob = j0 + jlc;
    const long xibase = (long)bglob * 512 * 1536 + jglob;

    for (int t = 0; t < 512; ++t) {
        const float* hcur = g_hbuf[t & 1];
        float* hnxt = g_hbuf[(t & 1) ^ 1];

        // prefetch xi for this step (DRAM; independent of h_t)
        const long xio = xibase + (long)t * 1536;
        float xr = g_xi[xio];
        float xz = g_xi[xio + 512];
        float xn = g_xi[xio + 1024];

        // stage h tile: global fp32 -> smem bf16 hi/lo (+ fp32 stash of own cols)
        for (int v = tid; v < 2048; v += 256) {
            int r = v >> 7, kc = (v & 127) << 2;
            float4 x = __ldcg((const float4*)(hcur + (b0 + r) * 512 + kc));
            uint32_t h0, h1, l0, l1;
            cvt4(x, h0, h1, l0, l1);
            *(uint2*)&Hh[r * 520 + kc] = make_uint2(h0, h1);
            *(uint2*)&Hl[r * 520 + kc] = make_uint2(l0, l1);
            if ((kc >> 4) == jg) *(float4*)&Hf[r * 16 + (kc & 15)] = x;
        }
        __syncthreads();

        // MMA: M=16 (batch) x N=48 (gate rows) x K=64 (this warp's slice)
        float acc[6][4];
#pragma unroll
        for (int ni = 0; ni < 6; ni++)
#pragma unroll
            for (int q = 0; q < 4; q++) acc[ni][q] = 0.f;

#pragma unroll
        for (int ks = 0; ks < 4; ++ks) {
            const int k = k0w + ks * 16;
            uint32_t ah[4], al[4];
            ah[0] = *(const uint32_t*)&Hh[lr * 520 + k + lc];
            ah[1] = *(const uint32_t*)&Hh[(lr + 8) * 520 + k + lc];
            ah[2] = *(const uint32_t*)&Hh[lr * 520 + k + lc + 8];
            ah[3] = *(const uint32_t*)&Hh[(lr + 8) * 520 + k + lc + 8];
            al[0] = *(const uint32_t*)&Hl[lr * 520 + k + lc];
            al[1] = *(const uint32_t*)&Hl[(lr + 8) * 520 + k + lc];
            al[2] = *(const uint32_t*)&Hl[lr * 520 + k + lc + 8];
            al[3] = *(const uint32_t*)&Hl[(lr + 8) * 520 + k + lc + 8];
#pragma unroll
            for (int ni = 0; ni < 6; ++ni) {
                int n = ni * 8 + lr;
                uint32_t bh0 = *(const uint32_t*)&Wh[n * 520 + k + lc];
                uint32_t bh1 = *(const uint32_t*)&Wh[n * 520 + k + lc + 8];
                uint32_t bl0 = *(const uint32_t*)&Wl[n * 520 + k + lc];
                uint32_t bl1 = *(const uint32_t*)&Wl[n * 520 + k + lc + 8];
                mma_bf16(acc[ni], ah, bh0, bh1);
                mma_bf16(acc[ni], ah, bl0, bl1);
                mma_bf16(acc[ni], al, bh0, bh1);
            }
        }

        float* rw = Red + warp * 800;
#pragma unroll
        for (int ni = 0; ni < 6; ++ni) {
            int n = ni * 8 + (lane & 3) * 2;
            *(float2*)&rw[lr * 50 + n] = make_float2(acc[ni][0], acc[ni][1]);
            *(float2*)&rw[(lr + 8) * 50 + n] = make_float2(acc[ni][2], acc[ni][3]);
        }
        __syncthreads();

        // combine: one (b,j) per thread; reduce 8 warps' K-partials
        float hr = br, hz = bz, hn = bnn;
#pragma unroll
        for (int w = 0; w < 8; ++w) {
            hr += Red[w * 800 + blc * 50 + jlc];
            hz += Red[w * 800 + blc * 50 + 16 + jlc];
            hn += Red[w * 800 + blc * 50 + 32 + jlc];
        }
        float hold = Hf[blc * 16 + jlc];
        float r = 1.f / (1.f + expf(-(xr + hr)));
        float z = 1.f / (1.f + expf(-(xz + hz)));
        float n = tanhf(xn + r * hn);
        float hnew = (1.f - z) * n + z * hold;
        __stcg(&hnxt[bglob * 512 + jglob], hnew);

        // ---- grid-wide barrier; g_dec store deferred past fence+arrive ----
        __syncthreads();
        unsigned old_arr = 0;
        if (tid == 0) {
            __threadfence();
            old_arr = atomicAdd(&g_bar[0], 1u);
        }
        g_dec[((long)(bglob * 512 + t)) * 512 + jglob] = hnew;  // off critical path
        if (tid == 0) {
            unsigned want = (unsigned)t + 1u;
            if (old_arr == (unsigned)t * 128u + 127u) {
                atomicExch(&g_bar[1], want);
            } else {
                while (*(volatile unsigned*)&g_bar[1] < want) { }
            }
            __threadfence();
        }
        __syncthreads();
    }
}

// ======================================================================
// Softmax over S=512 per (b,t) row, with encoder mask (True => -inf).
// ======================================================================
__global__ void __launch_bounds__(256) softmax_k(float* __restrict__ sc,
                                                 const unsigned char* __restrict__ mask)
{
    const int row = blockIdx.x;
    const int b = row >> 9;
    float* p = sc + (long)row * 512;
    const unsigned char* mp = mask + b * 512;
    const int tid = threadIdx.x;

    const float NEG_INF = -__int_as_float(0x7f800000);
    float v0 = p[tid], v1 = p[tid + 256];
    bool m0 = mp[tid] != 0, m1 = mp[tid + 256] != 0;
    if (m0) v0 = NEG_INF;
    if (m1) v1 = NEG_INF;

    __shared__ float red[8];
    __shared__ float bcast;

    float mx = fmaxf(v0, v1);
#pragma unroll
    for (int o = 16; o; o >>= 1) mx = fmaxf(mx, __shfl_xor_sync(0xffffffffu, mx, o));
    if ((tid & 31) == 0) red[tid >> 5] = mx;
    __syncthreads();
    if (tid < 8) {
        float x = red[tid];
#pragma unroll
        for (int o = 4; o; o >>= 1) x = fmaxf(x, __shfl_xor_sync(0xffu, x, o));
        if (tid == 0) bcast = x;
    }
    __syncthreads();
    mx = bcast;

    float e0 = m0 ? 0.f : __expf(v0 - mx);
    float e1 = m1 ? 0.f : __expf(v1 - mx);
    float s = e0 + e1;
#pragma unroll
    for (int o = 16; o; o >>= 1) s += __shfl_xor_sync(0xffffffffu, s, o);
    if ((tid & 31) == 0) red[tid >> 5] = s;
    __syncthreads();
    if (tid < 8) {
        float x = red[tid];
#pragma unroll
        for (int o = 4; o; o >>= 1) x += __shfl_xor_sync(0xffu, x, o);
        if (tid == 0) bcast = x;
    }
    __syncthreads();
    float inv = 1.f / bcast;
    p[tid] = e0 * inv;
    p[tid + 256] = e1 * inv;
}

__global__ void __launch_bounds__(256) copy_h_k(float* __restrict__ dst)
{
    int i = blockIdx.x * 256 + threadIdx.x;
    if (i < 64 * 512) dst[i] = g_hbuf[0][i];
}

// ======================================================================
// launch
// ======================================================================
extern "C" void kernel_launch(void* const* d_in, const int* in_sizes, int n_in,
                              void* d_out, int out_size)
{
    const float* X    = (const float*)d_in[0];   // [64,512,512]
    const float* Enc  = (const float*)d_in[1];   // [64,512,512]
    const unsigned char* Mask = (const unsigned char*)d_in[2];  // [64,512] bool
    const float* Wih  = (const float*)d_in[3];   // [1536,512]
    const float* Whh  = (const float*)d_in[4];   // [1536,512]
    const float* bih  = (const float*)d_in[5];   // [1536]
    const float* bhh  = (const float*)d_in[6];   // [1536]
    const float* Wao  = (const float*)d_in[7];   // [512,1024]
    const float* bao  = (const float*)d_in[8];   // [512]
    const float* Wd   = (const float*)d_in[9];   // [512,512]
    const float* bd   = (const float*)d_in[10];  // [512]
    float* out = (float*)d_out;

    void *p_xi, *p_dec, *p_sc, *p_mix, *p_o1, *p_enct, *p_h, *p_bar;
    cudaGetSymbolAddress(&p_xi, g_xi);
    cudaGetSymbolAddress(&p_dec, g_dec);
    cudaGetSymbolAddress(&p_sc, g_scores);
    cudaGetSymbolAddress(&p_mix, g_mix);
    cudaGetSymbolAddress(&p_o1, g_out1);
    cudaGetSymbolAddress(&p_enct, g_enct);
    cudaGetSymbolAddress(&p_h, g_hbuf);
    cudaGetSymbolAddress(&p_bar, g_bar);

    float* xi = (float*)p_xi;
    float* dec = (float*)p_dec;
    float* sc = (float*)p_sc;
    float* mix = (float*)p_mix;
    float* o1 = (float*)p_o1;
    float* enct = (float*)p_enct;

    cudaFuncSetAttribute(gru_scan, cudaFuncAttributeMaxDynamicSharedMemorySize, GRU_SMEM_BYTES);
    cudaFuncSetAttribute(tgemm_k<0>, cudaFuncAttributeMaxDynamicSharedMemorySize, TG_SMEM_BYTES);
    cudaFuncSetAttribute(tgemm_k<1>, cudaFuncAttributeMaxDynamicSharedMemorySize, TG_SMEM_BYTES);
    cudaFuncSetAttribute(tgemm_k<2>, cudaFuncAttributeMaxDynamicSharedMemorySize, TG_SMEM_BYTES);

    cudaMemsetAsync(p_h, 0, 64 * 512 * sizeof(float));
    cudaMemsetAsync(p_bar, 0, 2 * sizeof(unsigned));

    const int KBIG = 1 << 30;

    // 0) EncT = transpose(Enc) per batch  [B,H,S]
    transp_k<<<dim3(16, 16, 64), dim3(32, 8)>>>(Enc, enct);

    // 1) xi = X @ Wih^T + bih : [32768,1536]
    tgemm_k<1><<<dim3(12, 256, 1), 256, TG_SMEM_BYTES>>>(
        X, X, KBIG, 512, Wih, 512, bih, xi, 1536, 512, 0, 0, 0);

    // 2) GRU scan -> g_dec, h_last in g_hbuf[0]
    gru_scan<<<128, 256, GRU_SMEM_BYTES>>>(Whh, bhh);

    // 3) scores[b] = dec[b] @ enc[b]^T : 64 x [512,512]
    tgemm_k<0><<<dim3(4, 4, 64), 256, TG_SMEM_BYTES>>>(
        dec, dec, KBIG, 512, Enc, 512, nullptr, sc, 512, 512,
        262144L, 262144L, 262144L);

    // 4) softmax over S (with mask)
    softmax_k<<<64 * 512, 256>>>(sc, Mask);

    // 5) mix[b] = attn[b] @ enc[b] = attn[b] @ encT[b]^T : 64 x [512,512]
    tgemm_k<0><<<dim3(4, 4, 64), 256, TG_SMEM_BYTES>>>(
        sc, sc, KBIG, 512, enct, 512, nullptr, mix, 512, 512,
        262144L, 262144L, 262144L);

    // 6) out1 = tanh(concat(mix, dec) @ Wao^T + bao) : [32768,512], K=1024
    tgemm_k<2><<<dim3(4, 256, 1), 256, TG_SMEM_BYTES>>>(
        mix, dec, 512, 512, Wao, 1024, bao, o1, 512, 1024, 0, 0, 0);

    // 7) final = out1 @ Wd^T + bd -> d_out
    tgemm_k<1><<<dim3(4, 256, 1), 256, TG_SMEM_BYTES>>>(
        o1, o1, KBIG, 512, Wd, 512, bd, out, 512, 512, 0, 0, 0);

    // 8) h_last -> tail of d_out
    copy_h_k<<<128, 256>>>(out + (long)out_size - 64 * 512);
}

// round 7
// speedup vs baseline: 1.7837x; 1.0610x over previous
#include <cuda_runtime.h>
#include <cuda_bf16.h>
#include <math.h>
#include <stdint.h>

// Problem constants: B=64, T=512, S=512, E=512, H=512
// out = [B,T,H] (16,777,216 f32) followed by h_last [1,B,H] (32,768 f32)

// ---------------- scratch (static device globals; no allocs) ----------------
__device__ float g_xi[64L * 512 * 1536];     // input projection [B*T, 3H]
__device__ float g_dec[64L * 512 * 512];     // GRU outputs      [B*T, H]
__device__ float g_scores[64L * 512 * 512];  // scores / attn    [B, T, S]
__device__ float g_mix[64L * 512 * 512];     // attention mix    [B*T, H]
__device__ float g_out1[64L * 512 * 512];    // tanh(...)        [B*T, H]
__device__ float g_enct[64L * 512 * 512];    // Enc transposed   [B, H, S]
__device__ float g_hbuf[2][64 * 512];        // double-buffered hidden state
__device__ unsigned g_barc[4 * 32];          // per-bg arrival counters (padded)
__device__ unsigned g_gen4[4 * 32];          // per-bg generation (padded)

// ======================================================================
// Shared helpers
// ======================================================================
__device__ __forceinline__ void mma_bf16(float* c, const uint32_t* a,
                                         uint32_t b0, uint32_t b1) {
    asm volatile(
        "mma.sync.aligned.m16n8k16.row.col.f32.bf16.bf16.f32 "
        "{%0,%1,%2,%3}, {%4,%5,%6,%7}, {%8,%9}, {%0,%1,%2,%3};"
        : "+f"(c[0]), "+f"(c[1]), "+f"(c[2]), "+f"(c[3])
        : "r"(a[0]), "r"(a[1]), "r"(a[2]), "r"(a[3]), "r"(b0), "r"(b1));
}

__device__ __forceinline__ void ldsm_x4(uint32_t addr, uint32_t& r0, uint32_t& r1,
                                        uint32_t& r2, uint32_t& r3) {
    asm volatile("ldmatrix.sync.aligned.m8n8.x4.shared.b16 {%0,%1,%2,%3}, [%4];"
                 : "=r"(r0), "=r"(r1), "=r"(r2), "=r"(r3) : "r"(addr));
}

__device__ __forceinline__ uint32_t cvta_smem(const void* p) {
    uint32_t a;
    asm("{ .reg .u64 t; cvta.to.shared.u64 t, %1; cvt.u32.u64 %0, t; }"
        : "=r"(a) : "l"(p));
    return a;
}

__device__ __forceinline__ void cvt4(const float4 x, uint32_t& hi, uint32_t& hi2,
                                     uint32_t& lo, uint32_t& lo2) {
    __nv_bfloat162 h0 = __floats2bfloat162_rn(x.x, x.y);
    __nv_bfloat162 h1 = __floats2bfloat162_rn(x.z, x.w);
    __nv_bfloat162 l0 = __floats2bfloat162_rn(x.x - __bfloat162float(h0.x),
                                              x.y - __bfloat162float(h0.y));
    __nv_bfloat162 l1 = __floats2bfloat162_rn(x.z - __bfloat162float(h1.x),
                                              x.w - __bfloat162float(h1.y));
    hi = *reinterpret_cast<uint32_t*>(&h0);
    hi2 = *reinterpret_cast<uint32_t*>(&h1);
    lo = *reinterpret_cast<uint32_t*>(&l0);
    lo2 = *reinterpret_cast<uint32_t*>(&l1);
}

// ======================================================================
// bf16 HMMA split-precision GEMM, ldmatrix frags, reg prefetch, 2-stage smem.
//   C[m,n] = act( sum_k A[m,k] * B[n,k] + bias[n] )    (B is [N,K] row-major)
// C = Ah*Bh + Ah*Bl + Al*Bh (~1e-5 rel err). Concat via A2/ksplit.
// ACT: 0=none, 1=bias, 2=bias+tanh. Tile 128x128, K-chunk 32, 8 warps.
// ======================================================================
#define APAD 40  // row stride in bf16
#define TG_TILE (128 * APAD)                      // one [128][APAD] plane (bf16)
#define TG_SMEM_BYTES (2 * 2 * 2 * TG_TILE * 2)   // stages*(A,B)*(hi,lo)*plane*2B

template <int ACT>
__global__ void __launch_bounds__(256, 2) tgemm_k(
    const float* __restrict__ A, const float* __restrict__ A2, int ksplit, int lda,
    const float* __restrict__ Bm, int ldb,
    const float* __restrict__ bias,
    float* __restrict__ C, int ldc,
    int K, long sA, long sB, long sC)
{
    extern __shared__ __nv_bfloat16 smtg[];
    // layout: [stage][A:0/B:1][hi:0/lo:1][row][APAD]
    auto plane = [&](int st, int ab, int h) -> __nv_bfloat16* {
        return smtg + (((st * 2 + ab) * 2 + h) * TG_TILE);
    };
    const uint32_t smb = cvta_smem(smtg);
    auto planeA = [&](int st, int ab, int h) -> uint32_t {
        return smb + (uint32_t)(((st * 2 + ab) * 2 + h) * TG_TILE) * 2u;
    };

    const int tid = threadIdx.x, wid = tid >> 5, lane = tid & 31;
    const int m0 = blockIdx.y * 128, n0 = blockIdx.x * 128;
    const long zb = blockIdx.z;
    A += zb * sA; A2 += zb * sA; Bm += zb * sB; C += zb * sC;

    const int wm = wid & 3;        // 4 m-slices of 32
    const int wn = wid >> 2;       // 2 n-slices of 64
    const int lr = lane >> 2;      // 0..7

    // ldmatrix per-lane byte offsets (within a plane)
    const uint32_t a_off = ((uint32_t)(wm * 32 + (lane & 15)) * APAD +
                            (uint32_t)((lane >> 4) << 3)) * 2u;
    const uint32_t b_off = ((uint32_t)(wn * 64 + ((lane >> 4) << 3) + (lane & 7)) * APAD +
                            (uint32_t)(((lane >> 3) & 1) << 3)) * 2u;

    const int ldr = tid >> 1;            // loader row 0..127
    const int ldc0 = (tid & 1) * 16;     // loader col 0 or 16

    float acc[2][8][4];
#pragma unroll
    for (int mi = 0; mi < 2; mi++)
#pragma unroll
        for (int ni = 0; ni < 8; ni++)
#pragma unroll
            for (int q = 0; q < 4; q++) acc[mi][ni][q] = 0.f;

    float4 pa[4], pb[4];
    {
        const float* sa = A + (long)(m0 + ldr) * lda + ldc0;
        const float* sb = Bm + (long)(n0 + ldr) * ldb + ldc0;
#pragma unroll
        for (int i = 0; i < 4; i++) {
            pa[i] = *(const float4*)(sa + i * 4);
            pb[i] = *(const float4*)(sb + i * 4);
        }
    }
    {
        __nv_bfloat16 *ah = plane(0, 0, 0), *al = plane(0, 0, 1);
        __nv_bfloat16 *bh = plane(0, 1, 0), *bl = plane(0, 1, 1);
#pragma unroll
        for (int i = 0; i < 4; i++) {
            uint32_t h0, h1, l0, l1;
            int c = ldc0 + i * 4;
            cvt4(pa[i], h0, h1, l0, l1);
            *(uint2*)&ah[ldr * APAD + c] = make_uint2(h0, h1);
            *(uint2*)&al[ldr * APAD + c] = make_uint2(l0, l1);
            cvt4(pb[i], h0, h1, l0, l1);
            *(uint2*)&bh[ldr * APAD + c] = make_uint2(h0, h1);
            *(uint2*)&bl[ldr * APAD + c] = make_uint2(l0, l1);
        }
    }
    __syncthreads();

    const int nchunks = K >> 5;
    for (int ch = 0; ch < nchunks; ++ch) {
        const bool more = (ch + 1 < nchunks);
        if (more) {
            const int kg0 = (ch + 1) << 5;
            const float* Ab = A;
            int kc = kg0;
            if (kg0 >= ksplit) { Ab = A2; kc = kg0 - ksplit; }
            const float* sa = Ab + (long)(m0 + ldr) * lda + kc + ldc0;
            const float* sb = Bm + (long)(n0 + ldr) * ldb + kg0 + ldc0;
#pragma unroll
            for (int i = 0; i < 4; i++) {
                pa[i] = *(const float4*)(sa + i * 4);
                pb[i] = *(const float4*)(sb + i * 4);
            }
        }

        // ---- MMA on current stage (ldmatrix frags) ----
        const int st = ch & 1;
        const uint32_t AhA = planeA(st, 0, 0), AlA = planeA(st, 0, 1);
        const uint32_t BhA = planeA(st, 1, 0), BlA = planeA(st, 1, 1);
#pragma unroll
        for (int ks = 0; ks < 2; ++ks) {
            const uint32_t kb = (uint32_t)(ks * 16) * 2u;
            uint32_t afr[2][2][4];  // [hi/lo][mi][reg]
#pragma unroll
            for (int mi = 0; mi < 2; mi++) {
                uint32_t ao = a_off + (uint32_t)(mi * 16 * APAD) * 2u + kb;
                ldsm_x4(AhA + ao, afr[0][mi][0], afr[0][mi][1], afr[0][mi][2], afr[0][mi][3]);
                ldsm_x4(AlA + ao, afr[1][mi][0], afr[1][mi][1], afr[1][mi][2], afr[1][mi][3]);
            }
#pragma unroll
            for (int p = 0; p < 4; p++) {
                uint32_t bo = b_off + (uint32_t)(p * 16 * APAD) * 2u + kb;
                uint32_t bh0, bh1, bh2, bh3, bl0, bl1, bl2, bl3;
                ldsm_x4(BhA + bo, bh0, bh1, bh2, bh3);
                ldsm_x4(BlA + bo, bl0, bl1, bl2, bl3);
#pragma unroll
                for (int mi = 0; mi < 2; mi++) {
                    mma_bf16(acc[mi][2 * p + 0], afr[0][mi], bh0, bh1);
                    mma_bf16(acc[mi][2 * p + 0], afr[0][mi], bl0, bl1);
                    mma_bf16(acc[mi][2 * p + 0], afr[1][mi], bh0, bh1);
                    mma_bf16(acc[mi][2 * p + 1], afr[0][mi], bh2, bh3);
                    mma_bf16(acc[mi][2 * p + 1], afr[0][mi], bl2, bl3);
                    mma_bf16(acc[mi][2 * p + 1], afr[1][mi], bh2, bh3);
                }
            }
        }

        if (more) {
            const int ns = st ^ 1;
            __nv_bfloat16 *ah = plane(ns, 0, 0), *al = plane(ns, 0, 1);
            __nv_bfloat16 *bh = plane(ns, 1, 0), *bl = plane(ns, 1, 1);
#pragma unroll
            for (int i = 0; i < 4; i++) {
                uint32_t h0, h1, l0, l1;
                int c = ldc0 + i * 4;
                cvt4(pa[i], h0, h1, l0, l1);
                *(uint2*)&ah[ldr * APAD + c] = make_uint2(h0, h1);
                *(uint2*)&al[ldr * APAD + c] = make_uint2(l0, l1);
                cvt4(pb[i], h0, h1, l0, l1);
                *(uint2*)&bh[ldr * APAD + c] = make_uint2(h0, h1);
                *(uint2*)&bl[ldr * APAD + c] = make_uint2(l0, l1);
            }
            __syncthreads();
        }
    }

    // ---- epilogue ----
#pragma unroll
    for (int mi = 0; mi < 2; mi++) {
#pragma unroll
        for (int ni = 0; ni < 8; ni++) {
            int n = n0 + wn * 64 + ni * 8 + (lane & 3) * 2;
            float b0 = 0.f, b1 = 0.f;
            if (ACT >= 1) { b0 = bias[n]; b1 = bias[n + 1]; }
#pragma unroll
            for (int half = 0; half < 2; half++) {
                int m = m0 + wm * 32 + mi * 16 + lr + half * 8;
                float v0 = acc[mi][ni][half * 2 + 0] + b0;
                float v1 = acc[mi][ni][half * 2 + 1] + b1;
                if (ACT == 2) { v0 = tanhf(v0); v1 = tanhf(v1); }
                *(float2*)(C + (long)m * ldc + n) = make_float2(v0, v1);
            }
        }
    }
}

// ======================================================================
// Transpose Enc [B,S,H] -> EncT [B,H,S] (fp32)
// ======================================================================
__global__ void __launch_bounds__(256) transp_k(const float* __restrict__ src,
                                                float* __restrict__ dst)
{
    __shared__ float t[32][33];
    const int b = blockIdx.z;
    const int s0 = blockIdx.y * 32, h0 = blockIdx.x * 32;
    const float* S = src + ((long)b << 18);
    float* D = dst + ((long)b << 18);
    const int x = threadIdx.x, y = threadIdx.y;
#pragma unroll
    for (int i = 0; i < 32; i += 8) t[y + i][x] = S[(long)(s0 + y + i) * 512 + h0 + x];
    __syncthreads();
#pragma unroll
    for (int i = 0; i < 32; i += 8) D[(long)(h0 + y + i) * 512 + s0 + x] = t[x][y + i];
}

// ======================================================================
// Persistent tensor-core GRU scan. 128 CTAs x 256 threads.
// Per-bg (32-CTA) barriers: CTA (bg,jg) only depends on same-bg CTAs.
// ldmatrix fragment loads in the MMA stage.
// ======================================================================
#define GRU_SMEM_BYTES ((2 * 48 * 520 + 2 * 16 * 520) * 2 + (8 * 800 + 16 * 16) * 4)

__global__ void __launch_bounds__(256) gru_scan(const float* __restrict__ Whh,
                                                const float* __restrict__ bhh)
{
    extern __shared__ char smg[];
    __nv_bfloat16* Wh = (__nv_bfloat16*)smg;              // [48][520]
    __nv_bfloat16* Wl = Wh + 48 * 520;
    __nv_bfloat16* Hh = Wl + 48 * 520;                    // [16][520]
    __nv_bfloat16* Hl = Hh + 16 * 520;
    float* Red = (float*)(Hl + 16 * 520);                 // [8][800] (row stride 50)
    float* Hf = Red + 8 * 800;                            // [16][16] fp32 h_old chunk

    const uint32_t WhA = cvta_smem(Wh), WlA = cvta_smem(Wl);
    const uint32_t HhA = cvta_smem(Hh), HlA = cvta_smem(Hl);

    const int tid = threadIdx.x;
    const int bg = blockIdx.x >> 5;   // 0..3
    const int jg = blockIdx.x & 31;   // 0..31
    const int b0 = bg * 16, j0 = jg * 16;

    // Load + split-convert W slice once
    for (int v = tid; v < 48 * 128; v += 256) {
        int rowid = v >> 7, kc = (v & 127) << 2;
        int gate = rowid >> 4, jl = rowid & 15;
        float4 x = *(const float4*)(Whh + (long)(gate * 512 + j0 + jl) * 512 + kc);
        uint32_t h0, h1, l0, l1;
        cvt4(x, h0, h1, l0, l1);
        *(uint2*)&Wh[rowid * 520 + kc] = make_uint2(h0, h1);
        *(uint2*)&Wl[rowid * 520 + kc] = make_uint2(l0, l1);
    }

    const int warp = tid >> 5, lane = tid & 31;
    const int lr = lane >> 2;
    const int k0w = warp << 6;   // 64-wide K slice per warp

    // ldmatrix per-lane byte offsets (stride 520 bf16)
    const uint32_t a_off = ((uint32_t)(lane & 15) * 520 +
                            (uint32_t)((lane >> 4) << 3)) * 2u;
    const uint32_t b_off = ((uint32_t)(((lane >> 4) << 3) + (lane & 7)) * 520 +
                            (uint32_t)(((lane >> 3) & 1) << 3)) * 2u;

    const int blc = tid >> 4, jlc = tid & 15;   // combine-phase mapping
    const float br = bhh[j0 + jlc];
    const float bz = bhh[512 + j0 + jlc];
    const float bnn = bhh[1024 + j0 + jlc];
    const int bglob = b0 + blc, jglob = j0 + jlc;
    const long xibase = (long)bglob * 512 * 1536 + jglob;

    for (int t = 0; t < 512; ++t) {
        const float* hcur = g_hbuf[t & 1];
        float* hnxt = g_hbuf[(t & 1) ^ 1];

        // prefetch xi (DRAM; independent of h_t)
        const long xio = xibase + (long)t * 1536;
        float xr = g_xi[xio];
        float xz = g_xi[xio + 512];
        float xn = g_xi[xio + 1024];

        // stage h tile: global fp32 -> smem bf16 hi/lo (+ fp32 stash of own cols)
        for (int v = tid; v < 2048; v += 256) {
            int r = v >> 7, kc = (v & 127) << 2;
            float4 x = __ldcg((const float4*)(hcur + (b0 + r) * 512 + kc));
            uint32_t h0, h1, l0, l1;
            cvt4(x, h0, h1, l0, l1);
            *(uint2*)&Hh[r * 520 + kc] = make_uint2(h0, h1);
            *(uint2*)&Hl[r * 520 + kc] = make_uint2(l0, l1);
            if ((kc >> 4) == jg) *(float4*)&Hf[r * 16 + (kc & 15)] = x;
        }
        __syncthreads();

        // MMA: M=16 (batch) x N=48 (gate rows) x K=64 (this warp's slice)
        float acc[6][4];
#pragma unroll
        for (int ni = 0; ni < 6; ni++)
#pragma unroll
            for (int q = 0; q < 4; q++) acc[ni][q] = 0.f;

#pragma unroll
        for (int ks = 0; ks < 4; ++ks) {
            const uint32_t kb = (uint32_t)(k0w + ks * 16) * 2u;
            uint32_t ah[4], al[4];
            ldsm_x4(HhA + a_off + kb, ah[0], ah[1], ah[2], ah[3]);
            ldsm_x4(HlA + a_off + kb, al[0], al[1], al[2], al[3]);
#pragma unroll
            for (int p = 0; p < 3; ++p) {
                uint32_t bo = b_off + (uint32_t)(p * 16 * 520) * 2u + kb;
                uint32_t bh0, bh1, bh2, bh3, bl0, bl1, bl2, bl3;
                ldsm_x4(WhA + bo, bh0, bh1, bh2, bh3);
                ldsm_x4(WlA + bo, bl0, bl1, bl2, bl3);
                mma_bf16(acc[2 * p + 0], ah, bh0, bh1);
                mma_bf16(acc[2 * p + 0], ah, bl0, bl1);
                mma_bf16(acc[2 * p + 0], al, bh0, bh1);
                mma_bf16(acc[2 * p + 1], ah, bh2, bh3);
                mma_bf16(acc[2 * p + 1], ah, bl2, bl3);
                mma_bf16(acc[2 * p + 1], al, bh2, bh3);
            }
        }

        float* rw = Red + warp * 800;
#pragma unroll
        for (int ni = 0; ni < 6; ++ni) {
            int n = ni * 8 + (lane & 3) * 2;
            *(float2*)&rw[lr * 50 + n] = make_float2(acc[ni][0], acc[ni][1]);
            *(float2*)&rw[(lr + 8) * 50 + n] = make_float2(acc[ni][2], acc[ni][3]);
        }
        __syncthreads();

        // combine: one (b,j) per thread; reduce 8 warps' K-partials
        float hr = br, hz = bz, hn = bnn;
#pragma unroll
        for (int w = 0; w < 8; ++w) {
            hr += Red[w * 800 + blc * 50 + jlc];
            hz += Red[w * 800 + blc * 50 + 16 + jlc];
            hn += Red[w * 800 + blc * 50 + 32 + jlc];
        }
        float hold = Hf[blc * 16 + jlc];
        float r = 1.f / (1.f + expf(-(xr + hr)));
        float z = 1.f / (1.f + expf(-(xz + hz)));
        float n = tanhf(xn + r * hn);
        float hnew = (1.f - z) * n + z * hold;
        __stcg(&hnxt[bglob * 512 + jglob], hnew);

        // ---- per-bg barrier (32 CTAs); g_dec store off the fence path ----
        __syncthreads();
        unsigned old_arr = 0;
        if (tid == 0) {
            __threadfence();
            old_arr = atomicAdd(&g_barc[bg * 32], 1u);
        }
        g_dec[((long)(bglob * 512 + t)) * 512 + jglob] = hnew;
        if (tid == 0) {
            unsigned want = (unsigned)t + 1u;
            if (old_arr == (unsigned)t * 32u + 31u) {
                atomicExch(&g_gen4[bg * 32], want);
            } else {
                while (*(volatile unsigned*)&g_gen4[bg * 32] < want) { }
            }
            __threadfence();
        }
        __syncthreads();
    }
}

// ======================================================================
// Softmax over S=512 per (b,t) row, with encoder mask (True => -inf).
// ======================================================================
__global__ void __launch_bounds__(256) softmax_k(float* __restrict__ sc,
                                                 const unsigned char* __restrict__ mask)
{
    const int row = blockIdx.x;
    const int b = row >> 9;
    float* p = sc + (long)row * 512;
    const unsigned char* mp = mask + b * 512;
    const int tid = threadIdx.x;

    const float NEG_INF = -__int_as_float(0x7f800000);
    float v0 = p[tid], v1 = p[tid + 256];
    bool m0 = mp[tid] != 0, m1 = mp[tid + 256] != 0;
    if (m0) v0 = NEG_INF;
    if (m1) v1 = NEG_INF;

    __shared__ float red[8];
    __shared__ float bcast;

    float mx = fmaxf(v0, v1);
#pragma unroll
    for (int o = 16; o; o >>= 1) mx = fmaxf(mx, __shfl_xor_sync(0xffffffffu, mx, o));
    if ((tid & 31) == 0) red[tid >> 5] = mx;
    __syncthreads();
    if (tid < 8) {
        float x = red[tid];
#pragma unroll
        for (int o = 4; o; o >>= 1) x = fmaxf(x, __shfl_xor_sync(0xffu, x, o));
        if (tid == 0) bcast = x;
    }
    __syncthreads();
    mx = bcast;

    float e0 = m0 ? 0.f : __expf(v0 - mx);
    float e1 = m1 ? 0.f : __expf(v1 - mx);
    float s = e0 + e1;
#pragma unroll
    for (int o = 16; o; o >>= 1) s += __shfl_xor_sync(0xffffffffu, s, o);
    if ((tid & 31) == 0) red[tid >> 5] = s;
    __syncthreads();
    if (tid < 8) {
        float x = red[tid];
#pragma unroll
        for (int o = 4; o; o >>= 1) x += __shfl_xor_sync(0xffu, x, o);
        if (tid == 0) bcast = x;
    }
    __syncthreads();
    float inv = 1.f / bcast;
    p[tid] = e0 * inv;
    p[tid + 256] = e1 * inv;
}

__global__ void __launch_bounds__(256) copy_h_k(float* __restrict__ dst)
{
    int i = blockIdx.x * 256 + threadIdx.x;
    if (i < 64 * 512) dst[i] = g_hbuf[0][i];
}

// ======================================================================
// launch
// ======================================================================
extern "C" void kernel_launch(void* const* d_in, const int* in_sizes, int n_in,
                              void* d_out, int out_size)
{
    const float* X    = (const float*)d_in[0];   // [64,512,512]
    const float* Enc  = (const float*)d_in[1];   // [64,512,512]
    const unsigned char* Mask = (const unsigned char*)d_in[2];  // [64,512] bool
    const float* Wih  = (const float*)d_in[3];   // [1536,512]
    const float* Whh  = (const float*)d_in[4];   // [1536,512]
    const float* bih  = (const float*)d_in[5];   // [1536]
    const float* bhh  = (const float*)d_in[6];   // [1536]
    const float* Wao  = (const float*)d_in[7];   // [512,1024]
    const float* bao  = (const float*)d_in[8];   // [512]
    const float* Wd   = (const float*)d_in[9];   // [512,512]
    const float* bd   = (const float*)d_in[10];  // [512]
    float* out = (float*)d_out;

    void *p_xi, *p_dec, *p_sc, *p_mix, *p_o1, *p_enct, *p_h, *p_barc, *p_gen;
    cudaGetSymbolAddress(&p_xi, g_xi);
    cudaGetSymbolAddress(&p_dec, g_dec);
    cudaGetSymbolAddress(&p_sc, g_scores);
    cudaGetSymbolAddress(&p_mix, g_mix);
    cudaGetSymbolAddress(&p_o1, g_out1);
    cudaGetSymbolAddress(&p_enct, g_enct);
    cudaGetSymbolAddress(&p_h, g_hbuf);
    cudaGetSymbolAddress(&p_barc, g_barc);
    cudaGetSymbolAddress(&p_gen, g_gen4);

    float* xi = (float*)p_xi;
    float* dec = (float*)p_dec;
    float* sc = (float*)p_sc;
    float* mix = (float*)p_mix;
    float* o1 = (float*)p_o1;
    float* enct = (float*)p_enct;

    cudaFuncSetAttribute(gru_scan, cudaFuncAttributeMaxDynamicSharedMemorySize, GRU_SMEM_BYTES);
    cudaFuncSetAttribute(tgemm_k<0>, cudaFuncAttributeMaxDynamicSharedMemorySize, TG_SMEM_BYTES);
    cudaFuncSetAttribute(tgemm_k<1>, cudaFuncAttributeMaxDynamicSharedMemorySize, TG_SMEM_BYTES);
    cudaFuncSetAttribute(tgemm_k<2>, cudaFuncAttributeMaxDynamicSharedMemorySize, TG_SMEM_BYTES);

    cudaMemsetAsync(p_h, 0, 64 * 512 * sizeof(float));
    cudaMemsetAsync(p_barc, 0, 4 * 32 * sizeof(unsigned));
    cudaMemsetAsync(p_gen, 0, 4 * 32 * sizeof(unsigned));

    const int KBIG = 1 << 30;

    // 0) EncT = transpose(Enc) per batch  [B,H,S]
    transp_k<<<dim3(16, 16, 64), dim3(32, 8)>>>(Enc, enct);

    // 1) xi = X @ Wih^T + bih : [32768,1536]
    tgemm_k<1><<<dim3(12, 256, 1), 256, TG_SMEM_BYTES>>>(
        X, X, KBIG, 512, Wih, 512, bih, xi, 1536, 512, 0, 0, 0);

    // 2) GRU scan -> g_dec, h_last in g_hbuf[0]
    gru_scan<<<128, 256, GRU_SMEM_BYTES>>>(Whh, bhh);

    // 3) scores[b] = dec[b] @ enc[b]^T : 64 x [512,512]
    tgemm_k<0><<<dim3(4, 4, 64), 256, TG_SMEM_BYTES>>>(
        dec, dec, KBIG, 512, Enc, 512, nullptr, sc, 512, 512,
        262144L, 262144L, 262144L);

    // 4) softmax over S (with mask)
    softmax_k<<<64 * 512, 256>>>(sc, Mask);

    // 5) mix[b] = attn[b] @ enc[b] = attn[b] @ encT[b]^T : 64 x [512,512]
    tgemm_k<0><<<dim3(4, 4, 64), 256, TG_SMEM_BYTES>>>(
        sc, sc, KBIG, 512, enct, 512, nullptr, mix, 512, 512,
        262144L, 262144L, 262144L);

    // 6) out1 = tanh(concat(mix, dec) @ Wao^T + bao) : [32768,512], K=1024
    tgemm_k<2><<<dim3(4, 256, 1), 256, TG_SMEM_BYTES>>>(
        mix, dec, 512, 512, Wao, 1024, bao, o1, 512, 1024, 0, 0, 0);

    // 7) final = out1 @ Wd^T + bd -> d_out
    tgemm_k<1><<<dim3(4, 256, 1), 256, TG_SMEM_BYTES>>>(
        o1, o1, KBIG, 512, Wd, 512, bd, out, 512, 512, 0, 0, 0);

    // 8) h_last -> tail of d_out
    copy_h_k<<<128, 256>>>(out + (long)out_size - 64 * 512);
}

// round 8
// speedup vs baseline: 1.8594x; 1.0424x over previous
#include <cuda_runtime.h>
#include <cuda_bf16.h>
#include <math.h>
#include <stdint.h>

// Problem constants: B=64, T=512, S=512, E=512, H=512
typedef __nv_bfloat16 bf16;

// ---------------- scratch (static device globals; no allocs) ----------------
__device__ float g_xi[64L * 512 * 1536];     // input projection [B*T, 3H] fp32
__device__ float g_scores[64L * 512 * 512];  // scores (pre-softmax) fp32
__device__ float g_hbuf[2][64 * 512];        // double-buffered hidden state
__device__ unsigned g_barc[4 * 32];          // per-bg arrival counters (padded)
__device__ unsigned g_gen4[4 * 32];          // per-bg generation (padded)

// bf16 hi/lo operand buffers
__device__ bf16 g_Xh[64L * 512 * 512], g_Xl[64L * 512 * 512];
__device__ bf16 g_Ench[64L * 512 * 512], g_Encl[64L * 512 * 512];
__device__ bf16 g_ETh[64L * 512 * 512], g_ETl[64L * 512 * 512];
__device__ bf16 g_dech[64L * 512 * 512], g_decl[64L * 512 * 512];
__device__ bf16 g_attnh[64L * 512 * 512], g_attnl[64L * 512 * 512];
__device__ bf16 g_mixh[64L * 512 * 512], g_mixl[64L * 512 * 512];
__device__ bf16 g_o1h[64L * 512 * 512], g_o1l[64L * 512 * 512];
__device__ bf16 g_Wihh[1536 * 512], g_Wihl[1536 * 512];
__device__ bf16 g_Waoh[512 * 1024], g_Waol[512 * 1024];
__device__ bf16 g_Wdh[512 * 512], g_Wdl[512 * 512];

// ======================================================================
// helpers
// ======================================================================
__device__ __forceinline__ void mma_bf16(float* c, const uint32_t* a,
                                         uint32_t b0, uint32_t b1) {
    asm volatile(
        "mma.sync.aligned.m16n8k16.row.col.f32.bf16.bf16.f32 "
        "{%0,%1,%2,%3}, {%4,%5,%6,%7}, {%8,%9}, {%0,%1,%2,%3};"
        : "+f"(c[0]), "+f"(c[1]), "+f"(c[2]), "+f"(c[3])
        : "r"(a[0]), "r"(a[1]), "r"(a[2]), "r"(a[3]), "r"(b0), "r"(b1));
}

__device__ __forceinline__ void ldsm_x4(uint32_t addr, uint32_t& r0, uint32_t& r1,
                                        uint32_t& r2, uint32_t& r3) {
    asm volatile("ldmatrix.sync.aligned.m8n8.x4.shared.b16 {%0,%1,%2,%3}, [%4];"
                 : "=r"(r0), "=r"(r1), "=r"(r2), "=r"(r3) : "r"(addr));
}

__device__ __forceinline__ uint32_t cvta_smem(const void* p) {
    uint32_t a;
    asm("{ .reg .u64 t; cvta.to.shared.u64 t, %1; cvt.u32.u64 %0, t; }"
        : "=r"(a) : "l"(p));
    return a;
}

__device__ __forceinline__ void cp16(uint32_t dst, const void* src) {
    asm volatile("cp.async.cg.shared.global [%0], [%1], 16;"
                 :: "r"(dst), "l"(src));
}
#define CP_COMMIT() asm volatile("cp.async.commit_group;" ::: "memory")
#define CP_WAIT1() asm volatile("cp.async.wait_group 1;" ::: "memory")

__device__ __forceinline__ void split2(float a, float b, uint32_t& hi, uint32_t& lo) {
    __nv_bfloat162 h = __floats2bfloat162_rn(a, b);
    __nv_bfloat162 l = __floats2bfloat162_rn(a - __bfloat162float(h.x),
                                             b - __bfloat162float(h.y));
    hi = *reinterpret_cast<uint32_t*>(&h);
    lo = *reinterpret_cast<uint32_t*>(&l);
}

__device__ __forceinline__ void cvt4(const float4 x, uint32_t& hi, uint32_t& hi2,
                                     uint32_t& lo, uint32_t& lo2) {
    split2(x.x, x.y, hi, lo);
    split2(x.z, x.w, hi2, lo2);
}

// ======================================================================
// cvt pass: fp32 -> bf16 hi/lo (elementwise, float4 granularity)
// ======================================================================
__global__ void __launch_bounds__(256) cvt_k(const float* __restrict__ src,
                                             bf16* __restrict__ dh,
                                             bf16* __restrict__ dl, long n4)
{
    long i = (long)blockIdx.x * 256 + threadIdx.x;
    long stride = (long)gridDim.x * 256;
    for (; i < n4; i += stride) {
        float4 x = *(const float4*)(src + i * 4);
        uint32_t h0, h1, l0, l1;
        cvt4(x, h0, h1, l0, l1);
        *(uint2*)(dh + i * 4) = make_uint2(h0, h1);
        *(uint2*)(dl + i * 4) = make_uint2(l0, l1);
    }
}

// ======================================================================
// Enc prep: Enc [B,S,H] fp32 -> Ench/Encl (same layout) + ETh/ETl ([B,H,S])
// ======================================================================
__global__ void __launch_bounds__(256) encprep_k(const float* __restrict__ src,
                                                 bf16* __restrict__ eh, bf16* __restrict__ el,
                                                 bf16* __restrict__ th, bf16* __restrict__ tl)
{
    __shared__ float t[32][33];
    const int b = blockIdx.z;
    const int s0 = blockIdx.y * 32, h0 = blockIdx.x * 32;
    const long base = (long)b << 18;
    const int x = threadIdx.x, y = threadIdx.y;
#pragma unroll
    for (int i = 0; i < 32; i += 8) {
        float v = src[base + (long)(s0 + y + i) * 512 + h0 + x];
        t[y + i][x] = v;
        bf16 hi = __float2bfloat16(v);
        eh[base + (long)(s0 + y + i) * 512 + h0 + x] = hi;
        el[base + (long)(s0 + y + i) * 512 + h0 + x] =
            __float2bfloat16(v - __bfloat162float(hi));
    }
    __syncthreads();
#pragma unroll
    for (int i = 0; i < 32; i += 8) {
        float v = t[x][y + i];
        bf16 hi = __float2bfloat16(v);
        th[base + (long)(h0 + y + i) * 512 + s0 + x] = hi;
        tl[base + (long)(h0 + y + i) * 512 + s0 + x] =
            __float2bfloat16(v - __bfloat162float(hi));
    }
}

// ======================================================================
// bf16 HMMA split GEMM: cp.async 3-stage pipeline, K-chunk 16, ldmatrix.
//   C[m,n] = act( sum_k A[m,k]*B[n,k] + bias[n] ),  A/B given as hi/lo bf16.
// Concat via A2/ksplit. ACT: 0=none,1=bias,2=bias+tanh. OBF: also emit C hi/lo.
// Tile 128x128, 8 warps (4m x 2n).
// ======================================================================
#define APC 24                              // row stride (bf16): 16 data + 8 pad
#define PLANE_B (128 * APC * 2)             // 6144 bytes per plane
#define STAGE_B (4 * PLANE_B)               // Ah, Al, Bh, Bl
#define TGB_SMEM (3 * STAGE_B)              // 73728 bytes

template <int ACT, int OBF>
__global__ void __launch_bounds__(256, 2) tgemm_bf(
    const bf16* __restrict__ Ah, const bf16* __restrict__ Al,
    const bf16* __restrict__ A2h, const bf16* __restrict__ A2l, int ksplit, int lda,
    const bf16* __restrict__ Bh, const bf16* __restrict__ Bl, int ldb,
    const float* __restrict__ bias,
    float* __restrict__ C, bf16* __restrict__ Ch, bf16* __restrict__ Cl, int ldc,
    int K, long sA, long sB, long sC)
{
    extern __shared__ char smraw[];
    const uint32_t smb = cvta_smem(smraw);

    const int tid = threadIdx.x, wid = tid >> 5, lane = tid & 31;
    const int m0 = blockIdx.y * 128, n0 = blockIdx.x * 128;
    const long zb = blockIdx.z;
    Ah += zb * sA; Al += zb * sA; A2h += zb * sA; A2l += zb * sA;
    Bh += zb * sB; Bl += zb * sB;
    if (OBF) { Ch += zb * sC; Cl += zb * sC; }
    else { C += zb * sC; }

    const int wm = wid & 3, wn = wid >> 2;
    const int lr = lane >> 2;

    // ldmatrix per-lane byte offsets within a plane (APC stride)
    const uint32_t a_off = ((uint32_t)(wm * 32 + (lane & 15)) * APC +
                            (uint32_t)((lane >> 4) << 3)) * 2u;
    const uint32_t b_off = ((uint32_t)(wn * 64 + ((lane >> 4) << 3) + (lane & 7)) * APC +
                            (uint32_t)(((lane >> 3) & 1) << 3)) * 2u;

    // loader mapping: each thread moves one 16B granule per plane
    const int ldrow = tid >> 1;         // 0..127
    const int ldh = tid & 1;            // 16B half of the 32B row payload

    const int nch = K >> 4;

    auto issue = [&](int ch) {
        if (ch < nch) {
            const int kg = ch << 4;
            const bf16* ah = Ah; const bf16* al = Al;
            int kc = kg;
            if (kg >= ksplit) { ah = A2h; al = A2l; kc = kg - ksplit; }
            const uint32_t stb = smb + (uint32_t)(ch % 3) * STAGE_B +
                                 (uint32_t)(ldrow * (APC * 2) + ldh * 16);
            cp16(stb,               ah + (long)(m0 + ldrow) * lda + kc + ldh * 8);
            cp16(stb + PLANE_B,     al + (long)(m0 + ldrow) * lda + kc + ldh * 8);
            cp16(stb + 2 * PLANE_B, Bh + (long)(n0 + ldrow) * ldb + kg + ldh * 8);
            cp16(stb + 3 * PLANE_B, Bl + (long)(n0 + ldrow) * ldb + kg + ldh * 8);
        }
        CP_COMMIT();
    };

    float acc[2][8][4];
#pragma unroll
    for (int mi = 0; mi < 2; mi++)
#pragma unroll
        for (int ni = 0; ni < 8; ni++)
#pragma unroll
            for (int q = 0; q < 4; q++) acc[mi][ni][q] = 0.f;

    issue(0);
    issue(1);

    for (int ch = 0; ch < nch; ++ch) {
        CP_WAIT1();
        __syncthreads();
        issue(ch + 2);   // overwrites stage used by MMA(ch-1); all warps past sync

        const uint32_t AhA = smb + (uint32_t)(ch % 3) * STAGE_B;
        const uint32_t AlA = AhA + PLANE_B;
        const uint32_t BhA = AhA + 2 * PLANE_B;
        const uint32_t BlA = AhA + 3 * PLANE_B;

        uint32_t afr[2][2][4];
#pragma unroll
        for (int mi = 0; mi < 2; mi++) {
            uint32_t ao = a_off + (uint32_t)(mi * 16 * APC) * 2u;
            ldsm_x4(AhA + ao, afr[0][mi][0], afr[0][mi][1], afr[0][mi][2], afr[0][mi][3]);
            ldsm_x4(AlA + ao, afr[1][mi][0], afr[1][mi][1], afr[1][mi][2], afr[1][mi][3]);
        }
#pragma unroll
        for (int p = 0; p < 4; p++) {
            uint32_t bo = b_off + (uint32_t)(p * 16 * APC) * 2u;
            uint32_t bh0, bh1, bh2, bh3, bl0, bl1, bl2, bl3;
            ldsm_x4(BhA + bo, bh0, bh1, bh2, bh3);
            ldsm_x4(BlA + bo, bl0, bl1, bl2, bl3);
#pragma unroll
            for (int mi = 0; mi < 2; mi++) {
                mma_bf16(acc[mi][2 * p + 0], afr[0][mi], bh0, bh1);
                mma_bf16(acc[mi][2 * p + 0], afr[0][mi], bl0, bl1);
                mma_bf16(acc[mi][2 * p + 0], afr[1][mi], bh0, bh1);
                mma_bf16(acc[mi][2 * p + 1], afr[0][mi], bh2, bh3);
                mma_bf16(acc[mi][2 * p + 1], afr[0][mi], bl2, bl3);
                mma_bf16(acc[mi][2 * p + 1], afr[1][mi], bh2, bh3);
            }
        }
    }

    // ---- epilogue ----
#pragma unroll
    for (int mi = 0; mi < 2; mi++) {
#pragma unroll
        for (int ni = 0; ni < 8; ni++) {
            int n = n0 + wn * 64 + ni * 8 + (lane & 3) * 2;
            float b0 = 0.f, b1 = 0.f;
            if (ACT >= 1) { b0 = bias[n]; b1 = bias[n + 1]; }
#pragma unroll
            for (int half = 0; half < 2; half++) {
                int m = m0 + wm * 32 + mi * 16 + lr + half * 8;
                float v0 = acc[mi][ni][half * 2 + 0] + b0;
                float v1 = acc[mi][ni][half * 2 + 1] + b1;
                if (ACT == 2) { v0 = tanhf(v0); v1 = tanhf(v1); }
                if (OBF) {
                    uint32_t hi, lo;
                    split2(v0, v1, hi, lo);
                    *(uint32_t*)(Ch + (long)m * ldc + n) = hi;
                    *(uint32_t*)(Cl + (long)m * ldc + n) = lo;
                } else {
                    *(float2*)(C + (long)m * ldc + n) = make_float2(v0, v1);
                }
            }
        }
    }
}

// ======================================================================
// Persistent tensor-core GRU scan (per-bg barriers, ldmatrix). Writes dec
// as bf16 hi/lo pairs.
// ======================================================================
#define GRU_SMEM_BYTES ((2 * 48 * 520 + 2 * 16 * 520) * 2 + (8 * 800 + 16 * 16) * 4)

__global__ void __launch_bounds__(256) gru_scan(const float* __restrict__ Whh,
                                                const float* __restrict__ bhh)
{
    extern __shared__ char smg[];
    bf16* Wh = (bf16*)smg;                  // [48][520]
    bf16* Wl = Wh + 48 * 520;
    bf16* Hh = Wl + 48 * 520;               // [16][520]
    bf16* Hl = Hh + 16 * 520;
    float* Red = (float*)(Hl + 16 * 520);   // [8][800] (row stride 50)
    float* Hf = Red + 8 * 800;              // [16][16] fp32 h_old chunk

    const uint32_t WhA = cvta_smem(Wh), WlA = cvta_smem(Wl);
    const uint32_t HhA = cvta_smem(Hh), HlA = cvta_smem(Hl);

    const int tid = threadIdx.x;
    const int bg = blockIdx.x >> 5;
    const int jg = blockIdx.x & 31;
    const int b0 = bg * 16, j0 = jg * 16;

    for (int v = tid; v < 48 * 128; v += 256) {
        int rowid = v >> 7, kc = (v & 127) << 2;
        int gate = rowid >> 4, jl = rowid & 15;
        float4 x = *(const float4*)(Whh + (long)(gate * 512 + j0 + jl) * 512 + kc);
        uint32_t h0, h1, l0, l1;
        cvt4(x, h0, h1, l0, l1);
        *(uint2*)&Wh[rowid * 520 + kc] = make_uint2(h0, h1);
        *(uint2*)&Wl[rowid * 520 + kc] = make_uint2(l0, l1);
    }

    const int warp = tid >> 5, lane = tid & 31;
    const int lr = lane >> 2;
    const int k0w = warp << 6;

    const uint32_t a_off = ((uint32_t)(lane & 15) * 520 +
                            (uint32_t)((lane >> 4) << 3)) * 2u;
    const uint32_t b_off = ((uint32_t)(((lane >> 4) << 3) + (lane & 7)) * 520 +
                            (uint32_t)(((lane >> 3) & 1) << 3)) * 2u;

    const int blc = tid >> 4, jlc = tid & 15;
    const float br = bhh[j0 + jlc];
    const float bz = bhh[512 + j0 + jlc];
    const float bnn = bhh[1024 + j0 + jlc];
    const int bglob = b0 + blc, jglob = j0 + jlc;
    const long xibase = (long)bglob * 512 * 1536 + jglob;

    for (int t = 0; t < 512; ++t) {
        const float* hcur = g_hbuf[t & 1];
        float* hnxt = g_hbuf[(t & 1) ^ 1];

        const long xio = xibase + (long)t * 1536;
        float xr = g_xi[xio];
        float xz = g_xi[xio + 512];
        float xn = g_xi[xio + 1024];

        for (int v = tid; v < 2048; v += 256) {
            int r = v >> 7, kc = (v & 127) << 2;
            float4 x = __ldcg((const float4*)(hcur + (b0 + r) * 512 + kc));
            uint32_t h0, h1, l0, l1;
            cvt4(x, h0, h1, l0, l1);
            *(uint2*)&Hh[r * 520 + kc] = make_uint2(h0, h1);
            *(uint2*)&Hl[r * 520 + kc] = make_uint2(l0, l1);
            if ((kc >> 4) == jg) *(float4*)&Hf[r * 16 + (kc & 15)] = x;
        }
        __syncthreads();

        float acc[6][4];
#pragma unroll
        for (int ni = 0; ni < 6; ni++)
#pragma unroll
            for (int q = 0; q < 4; q++) acc[ni][q] = 0.f;

#pragma unroll
        for (int ks = 0; ks < 4; ++ks) {
            const uint32_t kb = (uint32_t)(k0w + ks * 16) * 2u;
            uint32_t ah[4], al[4];
            ldsm_x4(HhA + a_off + kb, ah[0], ah[1], ah[2], ah[3]);
            ldsm_x4(HlA + a_off + kb, al[0], al[1], al[2], al[3]);
#pragma unroll
            for (int p = 0; p < 3; ++p) {
                uint32_t bo = b_off + (uint32_t)(p * 16 * 520) * 2u + kb;
                uint32_t bh0, bh1, bh2, bh3, bl0, bl1, bl2, bl3;
                ldsm_x4(WhA + bo, bh0, bh1, bh2, bh3);
                ldsm_x4(WlA + bo, bl0, bl1, bl2, bl3);
                mma_bf16(acc[2 * p + 0], ah, bh0, bh1);
                mma_bf16(acc[2 * p + 0], ah, bl0, bl1);
                mma_bf16(acc[2 * p + 0], al, bh0, bh1);
                mma_bf16(acc[2 * p + 1], ah, bh2, bh3);
                mma_bf16(acc[2 * p + 1], ah, bl2, bl3);
                mma_bf16(acc[2 * p + 1], al, bh2, bh3);
            }
        }

        float* rw = Red + warp * 800;
#pragma unroll
        for (int ni = 0; ni < 6; ++ni) {
            int n = ni * 8 + (lane & 3) * 2;
            *(float2*)&rw[lr * 50 + n] = make_float2(acc[ni][0], acc[ni][1]);
            *(float2*)&rw[(lr + 8) * 50 + n] = make_float2(acc[ni][2], acc[ni][3]);
        }
        __syncthreads();

        float hr = br, hz = bz, hn = bnn;
#pragma unroll
        for (int w = 0; w < 8; ++w) {
            hr += Red[w * 800 + blc * 50 + jlc];
            hz += Red[w * 800 + blc * 50 + 16 + jlc];
            hn += Red[w * 800 + blc * 50 + 32 + jlc];
        }
        float hold = Hf[blc * 16 + jlc];
        float r = 1.f / (1.f + expf(-(xr + hr)));
        float z = 1.f / (1.f + expf(-(xz + hz)));
        float n = tanhf(xn + r * hn);
        float hnew = (1.f - z) * n + z * hold;
        __stcg(&hnxt[bglob * 512 + jglob], hnew);

        __syncthreads();
        unsigned old_arr = 0;
        if (tid == 0) {
            __threadfence();
            old_arr = atomicAdd(&g_barc[bg * 32], 1u);
        }
        {   // dec hi/lo store — off the fence/arrive critical path
            long di = ((long)(bglob * 512 + t)) * 512 + jglob;
            bf16 hi = __float2bfloat16(hnew);
            g_dech[di] = hi;
            g_decl[di] = __float2bfloat16(hnew - __bfloat162float(hi));
        }
        if (tid == 0) {
            unsigned want = (unsigned)t + 1u;
            if (old_arr == (unsigned)t * 32u + 31u) {
                atomicExch(&g_gen4[bg * 32], want);
            } else {
                while (*(volatile unsigned*)&g_gen4[bg * 32] < want) { }
            }
            __threadfence();
        }
        __syncthreads();
    }
}

// ======================================================================
// Softmax over S=512 per (b,t) row, mask-aware; writes attn bf16 hi/lo.
// ======================================================================
__global__ void __launch_bounds__(256) softmax_k(const float* __restrict__ sc,
                                                 const unsigned char* __restrict__ mask)
{
    const int row = blockIdx.x;
    const int b = row >> 9;
    const float* p = sc + (long)row * 512;
    const unsigned char* mp = mask + b * 512;
    const int tid = threadIdx.x;

    const float NEG_INF = -__int_as_float(0x7f800000);
    float v0 = p[tid], v1 = p[tid + 256];
    bool m0 = mp[tid] != 0, m1 = mp[tid + 256] != 0;
    if (m0) v0 = NEG_INF;
    if (m1) v1 = NEG_INF;

    __shared__ float red[8];
    __shared__ float bcast;

    float mx = fmaxf(v0, v1);
#pragma unroll
    for (int o = 16; o; o >>= 1) mx = fmaxf(mx, __shfl_xor_sync(0xffffffffu, mx, o));
    if ((tid & 31) == 0) red[tid >> 5] = mx;
    __syncthreads();
    if (tid < 8) {
        float x = red[tid];
#pragma unroll
        for (int o = 4; o; o >>= 1) x = fmaxf(x, __shfl_xor_sync(0xffu, x, o));
        if (tid == 0) bcast = x;
    }
    __syncthreads();
    mx = bcast;

    float e0 = m0 ? 0.f : __expf(v0 - mx);
    float e1 = m1 ? 0.f : __expf(v1 - mx);
    float s = e0 + e1;
#pragma unroll
    for (int o = 16; o; o >>= 1) s += __shfl_xor_sync(0xffffffffu, s, o);
    if ((tid & 31) == 0) red[tid >> 5] = s;
    __syncthreads();
    if (tid < 8) {
        float x = red[tid];
#pragma unroll
        for (int o = 4; o; o >>= 1) x += __shfl_xor_sync(0xffu, x, o);
        if (tid == 0) bcast = x;
    }
    __syncthreads();
    float inv = 1.f / bcast;
    float a0 = e0 * inv, a1 = e1 * inv;
    long base = (long)row * 512;
    bf16 h0 = __float2bfloat16(a0);
    bf16 h1 = __float2bfloat16(a1);
    g_attnh[base + tid] = h0;
    g_attnl[base + tid] = __float2bfloat16(a0 - __bfloat162float(h0));
    g_attnh[base + tid + 256] = h1;
    g_attnl[base + tid + 256] = __float2bfloat16(a1 - __bfloat162float(h1));
}

__global__ void __launch_bounds__(256) copy_h_k(float* __restrict__ dst)
{
    int i = blockIdx.x * 256 + threadIdx.x;
    if (i < 64 * 512) dst[i] = g_hbuf[0][i];
}

// ======================================================================
// launch
// ======================================================================
extern "C" void kernel_launch(void* const* d_in, const int* in_sizes, int n_in,
                              void* d_out, int out_size)
{
    const float* X    = (const float*)d_in[0];
    const float* Enc  = (const float*)d_in[1];
    const unsigned char* Mask = (const unsigned char*)d_in[2];
    const float* Wih  = (const float*)d_in[3];
    const float* Whh  = (const float*)d_in[4];
    const float* bih  = (const float*)d_in[5];
    const float* bhh  = (const float*)d_in[6];
    const float* Wao  = (const float*)d_in[7];
    const float* bao  = (const float*)d_in[8];
    const float* Wd   = (const float*)d_in[9];
    const float* bd   = (const float*)d_in[10];
    float* out = (float*)d_out;

    void *p_xi, *p_sc, *p_h, *p_barc, *p_gen;
    cudaGetSymbolAddress(&p_xi, g_xi);
    cudaGetSymbolAddress(&p_sc, g_scores);
    cudaGetSymbolAddress(&p_h, g_hbuf);
    cudaGetSymbolAddress(&p_barc, g_barc);
    cudaGetSymbolAddress(&p_gen, g_gen4);
    float* xi = (float*)p_xi;
    float* sc = (float*)p_sc;

    // device addresses of bf16 buffers
#define GET(sym) ({ void* _p; cudaGetSymbolAddress(&_p, sym); (bf16*)_p; })
    bf16 *Xh = GET(g_Xh), *Xl = GET(g_Xl);
    bf16 *Eh = GET(g_Ench), *El = GET(g_Encl);
    bf16 *Th = GET(g_ETh), *Tl = GET(g_ETl);
    bf16 *Dh = GET(g_dech), *Dl = GET(g_decl);
    bf16 *Atth = GET(g_attnh), *Attl = GET(g_attnl);
    bf16 *Mh = GET(g_mixh), *Ml = GET(g_mixl);
    bf16 *Oh = GET(g_o1h), *Ol = GET(g_o1l);
    bf16 *Wih_h = GET(g_Wihh), *Wih_l = GET(g_Wihl);
    bf16 *Wao_h = GET(g_Waoh), *Wao_l = GET(g_Waol);
    bf16 *Wd_h = GET(g_Wdh), *Wd_l = GET(g_Wdl);
#undef GET

    cudaFuncSetAttribute(gru_scan, cudaFuncAttributeMaxDynamicSharedMemorySize, GRU_SMEM_BYTES);
    cudaFuncSetAttribute(tgemm_bf<1, 0>, cudaFuncAttributeMaxDynamicSharedMemorySize, TGB_SMEM);
    cudaFuncSetAttribute(tgemm_bf<0, 0>, cudaFuncAttributeMaxDynamicSharedMemorySize, TGB_SMEM);
    cudaFuncSetAttribute(tgemm_bf<0, 1>, cudaFuncAttributeMaxDynamicSharedMemorySize, TGB_SMEM);
    cudaFuncSetAttribute(tgemm_bf<2, 1>, cudaFuncAttributeMaxDynamicSharedMemorySize, TGB_SMEM);

    cudaMemsetAsync(p_h, 0, 64 * 512 * sizeof(float));
    cudaMemsetAsync(p_barc, 0, 4 * 32 * sizeof(unsigned));
    cudaMemsetAsync(p_gen, 0, 4 * 32 * sizeof(unsigned));

    const int KBIG = 1 << 30;

    // 0) operand prep (bf16 hi/lo)
    cvt_k<<<512, 256>>>(X, Xh, Xl, (64L * 512 * 512) / 4);
    cvt_k<<<64, 256>>>(Wih, Wih_h, Wih_l, (1536L * 512) / 4);
    cvt_k<<<64, 256>>>(Wao, Wao_h, Wao_l, (512L * 1024) / 4);
    cvt_k<<<32, 256>>>(Wd, Wd_h, Wd_l, (512L * 512) / 4);
    encprep_k<<<dim3(16, 16, 64), dim3(32, 8)>>>(Enc, Eh, El, Th, Tl);

    // 1) xi = X @ Wih^T + bih : [32768,1536] fp32
    tgemm_bf<1, 0><<<dim3(12, 256, 1), 256, TGB_SMEM>>>(
        Xh, Xl, Xh, Xl, KBIG, 512, Wih_h, Wih_l, 512, bih,
        xi, nullptr, nullptr, 1536, 512, 0, 0, 0);

    // 2) GRU scan -> dec hi/lo, h_last in g_hbuf[0]
    gru_scan<<<128, 256, GRU_SMEM_BYTES>>>(Whh, bhh);

    // 3) scores[b] = dec[b] @ enc[b]^T : fp32
    tgemm_bf<0, 0><<<dim3(4, 4, 64), 256, TGB_SMEM>>>(
        Dh, Dl, Dh, Dl, KBIG, 512, Eh, El, 512, nullptr,
        sc, nullptr, nullptr, 512, 512, 262144L, 262144L, 262144L);

    // 4) softmax (mask) -> attn hi/lo
    softmax_k<<<64 * 512, 256>>>(sc, Mask);

    // 5) mix[b] = attn[b] @ encT[b]^T : bf16 hi/lo out
    tgemm_bf<0, 1><<<dim3(4, 4, 64), 256, TGB_SMEM>>>(
        Atth, Attl, Atth, Attl, KBIG, 512, Th, Tl, 512, nullptr,
        nullptr, Mh, Ml, 512, 512, 262144L, 262144L, 262144L);

    // 6) o1 = tanh(concat(mix, dec) @ Wao^T + bao) : bf16 hi/lo out, K=1024
    tgemm_bf<2, 1><<<dim3(4, 256, 1), 256, TGB_SMEM>>>(
        Mh, Ml, Dh, Dl, 512, 512, Wao_h, Wao_l, 1024, bao,
        nullptr, Oh, Ol, 512, 1024, 0, 0, 0);

    // 7) final = o1 @ Wd^T + bd -> d_out fp32
    tgemm_bf<1, 0><<<dim3(4, 256, 1), 256, TGB_SMEM>>>(
        Oh, Ol, Oh, Ol, KBIG, 512, Wd_h, Wd_l, 512, bd,
        out, nullptr, nullptr, 512, 512, 0, 0, 0);

    // 8) h_last -> tail of d_out
    copy_h_k<<<128, 256>>>(out + (long)out_size - 64 * 512);
}

// round 9
// speedup vs baseline: 2.0393x; 1.0967x over previous
#include <cuda_runtime.h>
#include <cuda_bf16.h>
#include <math.h>
#include <stdint.h>

// Problem constants: B=64, T=512, S=512, E=512, H=512
typedef __nv_bfloat16 bf16;

// ---------------- scratch (static device globals; no allocs) ----------------
__device__ float g_xi[64L * 512 * 1536];     // input projection [B*T, 3H] fp32
__device__ float g_scores[64L * 512 * 512];  // scores (pre-softmax) fp32
__device__ bf16 g_hbh[2][64 * 512];          // hidden state hi (double buffered)
__device__ bf16 g_hbl[2][64 * 512];          // hidden state lo
__device__ unsigned g_barc[4 * 32];          // per-bg arrival counters (padded)

// bf16 hi/lo operand buffers
__device__ bf16 g_Xh[64L * 512 * 512], g_Xl[64L * 512 * 512];
__device__ bf16 g_Ench[64L * 512 * 512], g_Encl[64L * 512 * 512];
__device__ bf16 g_ETh[64L * 512 * 512], g_ETl[64L * 512 * 512];
__device__ bf16 g_dech[64L * 512 * 512], g_decl[64L * 512 * 512];
__device__ bf16 g_attnh[64L * 512 * 512], g_attnl[64L * 512 * 512];
__device__ bf16 g_mixh[64L * 512 * 512], g_mixl[64L * 512 * 512];
__device__ bf16 g_o1h[64L * 512 * 512], g_o1l[64L * 512 * 512];
__device__ bf16 g_Wihh[1536 * 512], g_Wihl[1536 * 512];
__device__ bf16 g_Waoh[512 * 1024], g_Waol[512 * 1024];
__device__ bf16 g_Wdh[512 * 512], g_Wdl[512 * 512];

// ======================================================================
// helpers
// ======================================================================
__device__ __forceinline__ void mma_bf16(float* c, const uint32_t* a,
                                         uint32_t b0, uint32_t b1) {
    asm volatile(
        "mma.sync.aligned.m16n8k16.row.col.f32.bf16.bf16.f32 "
        "{%0,%1,%2,%3}, {%4,%5,%6,%7}, {%8,%9}, {%0,%1,%2,%3};"
        : "+f"(c[0]), "+f"(c[1]), "+f"(c[2]), "+f"(c[3])
        : "r"(a[0]), "r"(a[1]), "r"(a[2]), "r"(a[3]), "r"(b0), "r"(b1));
}

__device__ __forceinline__ void ldsm_x4(uint32_t addr, uint32_t& r0, uint32_t& r1,
                                        uint32_t& r2, uint32_t& r3) {
    asm volatile("ldmatrix.sync.aligned.m8n8.x4.shared.b16 {%0,%1,%2,%3}, [%4];"
                 : "=r"(r0), "=r"(r1), "=r"(r2), "=r"(r3) : "r"(addr));
}

__device__ __forceinline__ uint32_t cvta_smem(const void* p) {
    uint32_t a;
    asm("{ .reg .u64 t; cvta.to.shared.u64 t, %1; cvt.u32.u64 %0, t; }"
        : "=r"(a) : "l"(p));
    return a;
}

__device__ __forceinline__ void cp16(uint32_t dst, const void* src) {
    asm volatile("cp.async.cg.shared.global [%0], [%1], 16;"
                 :: "r"(dst), "l"(src));
}
#define CP_COMMIT() asm volatile("cp.async.commit_group;" ::: "memory")
#define CP_WAIT1() asm volatile("cp.async.wait_group 1;" ::: "memory")
#define CP_WAIT0() asm volatile("cp.async.wait_group 0;" ::: "memory")

__device__ __forceinline__ void split2(float a, float b, uint32_t& hi, uint32_t& lo) {
    __nv_bfloat162 h = __floats2bfloat162_rn(a, b);
    __nv_bfloat162 l = __floats2bfloat162_rn(a - __bfloat162float(h.x),
                                             b - __bfloat162float(h.y));
    hi = *reinterpret_cast<uint32_t*>(&h);
    lo = *reinterpret_cast<uint32_t*>(&l);
}

__device__ __forceinline__ void cvt4(const float4 x, uint32_t& hi, uint32_t& hi2,
                                     uint32_t& lo, uint32_t& lo2) {
    split2(x.x, x.y, hi, lo);
    split2(x.z, x.w, hi2, lo2);
}

// ======================================================================
// cvt pass: fp32 -> bf16 hi/lo (elementwise, float4 granularity)
// ======================================================================
__global__ void __launch_bounds__(256) cvt_k(const float* __restrict__ src,
                                             bf16* __restrict__ dh,
                                             bf16* __restrict__ dl, long n4)
{
    long i = (long)blockIdx.x * 256 + threadIdx.x;
    long stride = (long)gridDim.x * 256;
    for (; i < n4; i += stride) {
        float4 x = *(const float4*)(src + i * 4);
        uint32_t h0, h1, l0, l1;
        cvt4(x, h0, h1, l0, l1);
        *(uint2*)(dh + i * 4) = make_uint2(h0, h1);
        *(uint2*)(dl + i * 4) = make_uint2(l0, l1);
    }
}

// ======================================================================
// Enc prep: Enc [B,S,H] fp32 -> Ench/Encl (same layout) + ETh/ETl ([B,H,S])
// ======================================================================
__global__ void __launch_bounds__(256) encprep_k(const float* __restrict__ src,
                                                 bf16* __restrict__ eh, bf16* __restrict__ el,
                                                 bf16* __restrict__ th, bf16* __restrict__ tl)
{
    __shared__ float t[32][33];
    const int b = blockIdx.z;
    const int s0 = blockIdx.y * 32, h0 = blockIdx.x * 32;
    const long base = (long)b << 18;
    const int x = threadIdx.x, y = threadIdx.y;
#pragma unroll
    for (int i = 0; i < 32; i += 8) {
        float v = src[base + (long)(s0 + y + i) * 512 + h0 + x];
        t[y + i][x] = v;
        bf16 hi = __float2bfloat16(v);
        eh[base + (long)(s0 + y + i) * 512 + h0 + x] = hi;
        el[base + (long)(s0 + y + i) * 512 + h0 + x] =
            __float2bfloat16(v - __bfloat162float(hi));
    }
    __syncthreads();
#pragma unroll
    for (int i = 0; i < 32; i += 8) {
        float v = t[x][y + i];
        bf16 hi = __float2bfloat16(v);
        th[base + (long)(h0 + y + i) * 512 + s0 + x] = hi;
        tl[base + (long)(h0 + y + i) * 512 + s0 + x] =
            __float2bfloat16(v - __bfloat162float(hi));
    }
}

// ======================================================================
// bf16 HMMA split GEMM: cp.async 3-stage pipeline, K-chunk 16, ldmatrix.
// (unchanged from R8 — known good)
// ======================================================================
#define APC 24
#define PLANE_B (128 * APC * 2)
#define STAGE_B (4 * PLANE_B)
#define TGB_SMEM (3 * STAGE_B)

template <int ACT, int OBF>
__global__ void __launch_bounds__(256, 2) tgemm_bf(
    const bf16* __restrict__ Ah, const bf16* __restrict__ Al,
    const bf16* __restrict__ A2h, const bf16* __restrict__ A2l, int ksplit, int lda,
    const bf16* __restrict__ Bh, const bf16* __restrict__ Bl, int ldb,
    const float* __restrict__ bias,
    float* __restrict__ C, bf16* __restrict__ Ch, bf16* __restrict__ Cl, int ldc,
    int K, long sA, long sB, long sC)
{
    extern __shared__ char smraw[];
    const uint32_t smb = cvta_smem(smraw);

    const int tid = threadIdx.x, wid = tid >> 5, lane = tid & 31;
    const int m0 = blockIdx.y * 128, n0 = blockIdx.x * 128;
    const long zb = blockIdx.z;
    Ah += zb * sA; Al += zb * sA; A2h += zb * sA; A2l += zb * sA;
    Bh += zb * sB; Bl += zb * sB;
    if (OBF) { Ch += zb * sC; Cl += zb * sC; }
    else { C += zb * sC; }

    const int wm = wid & 3, wn = wid >> 2;
    const int lr = lane >> 2;

    const uint32_t a_off = ((uint32_t)(wm * 32 + (lane & 15)) * APC +
                            (uint32_t)((lane >> 4) << 3)) * 2u;
    const uint32_t b_off = ((uint32_t)(wn * 64 + ((lane >> 4) << 3) + (lane & 7)) * APC +
                            (uint32_t)(((lane >> 3) & 1) << 3)) * 2u;

    const int ldrow = tid >> 1;
    const int ldh = tid & 1;

    const int nch = K >> 4;

    auto issue = [&](int ch) {
        if (ch < nch) {
            const int kg = ch << 4;
            const bf16* ah = Ah; const bf16* al = Al;
            int kc = kg;
            if (kg >= ksplit) { ah = A2h; al = A2l; kc = kg - ksplit; }
            const uint32_t stb = smb + (uint32_t)(ch % 3) * STAGE_B +
                                 (uint32_t)(ldrow * (APC * 2) + ldh * 16);
            cp16(stb,               ah + (long)(m0 + ldrow) * lda + kc + ldh * 8);
            cp16(stb + PLANE_B,     al + (long)(m0 + ldrow) * lda + kc + ldh * 8);
            cp16(stb + 2 * PLANE_B, Bh + (long)(n0 + ldrow) * ldb + kg + ldh * 8);
            cp16(stb + 3 * PLANE_B, Bl + (long)(n0 + ldrow) * ldb + kg + ldh * 8);
        }
        CP_COMMIT();
    };

    float acc[2][8][4];
#pragma unroll
    for (int mi = 0; mi < 2; mi++)
#pragma unroll
        for (int ni = 0; ni < 8; ni++)
#pragma unroll
            for (int q = 0; q < 4; q++) acc[mi][ni][q] = 0.f;

    issue(0);
    issue(1);

    for (int ch = 0; ch < nch; ++ch) {
        CP_WAIT1();
        __syncthreads();
        issue(ch + 2);

        const uint32_t AhA = smb + (uint32_t)(ch % 3) * STAGE_B;
        const uint32_t AlA = AhA + PLANE_B;
        const uint32_t BhA = AhA + 2 * PLANE_B;
        const uint32_t BlA = AhA + 3 * PLANE_B;

        uint32_t afr[2][2][4];
#pragma unroll
        for (int mi = 0; mi < 2; mi++) {
            uint32_t ao = a_off + (uint32_t)(mi * 16 * APC) * 2u;
            ldsm_x4(AhA + ao, afr[0][mi][0], afr[0][mi][1], afr[0][mi][2], afr[0][mi][3]);
            ldsm_x4(AlA + ao, afr[1][mi][0], afr[1][mi][1], afr[1][mi][2], afr[1][mi][3]);
        }
#pragma unroll
        for (int p = 0; p < 4; p++) {
            uint32_t bo = b_off + (uint32_t)(p * 16 * APC) * 2u;
            uint32_t bh0, bh1, bh2, bh3, bl0, bl1, bl2, bl3;
            ldsm_x4(BhA + bo, bh0, bh1, bh2, bh3);
            ldsm_x4(BlA + bo, bl0, bl1, bl2, bl3);
#pragma unroll
            for (int mi = 0; mi < 2; mi++) {
                mma_bf16(acc[mi][2 * p + 0], afr[0][mi], bh0, bh1);
                mma_bf16(acc[mi][2 * p + 0], afr[0][mi], bl0, bl1);
                mma_bf16(acc[mi][2 * p + 0], afr[1][mi], bh0, bh1);
                mma_bf16(acc[mi][2 * p + 1], afr[0][mi], bh2, bh3);
                mma_bf16(acc[mi][2 * p + 1], afr[0][mi], bl2, bl3);
                mma_bf16(acc[mi][2 * p + 1], afr[1][mi], bh2, bh3);
            }
        }
    }

    // ---- epilogue ----
#pragma unroll
    for (int mi = 0; mi < 2; mi++) {
#pragma unroll
        for (int ni = 0; ni < 8; ni++) {
            int n = n0 + wn * 64 + ni * 8 + (lane & 3) * 2;
            float b0 = 0.f, b1 = 0.f;
            if (ACT >= 1) { b0 = bias[n]; b1 = bias[n + 1]; }
#pragma unroll
            for (int half = 0; half < 2; half++) {
                int m = m0 + wm * 32 + mi * 16 + lr + half * 8;
                float v0 = acc[mi][ni][half * 2 + 0] + b0;
                float v1 = acc[mi][ni][half * 2 + 1] + b1;
                if (ACT == 2) { v0 = tanhf(v0); v1 = tanhf(v1); }
                if (OBF) {
                    uint32_t hi, lo;
                    split2(v0, v1, hi, lo);
                    *(uint32_t*)(Ch + (long)m * ldc + n) = hi;
                    *(uint32_t*)(Cl + (long)m * ldc + n) = lo;
                } else {
                    *(float2*)(C + (long)m * ldc + n) = make_float2(v0, v1);
                }
            }
        }
    }
}

// ======================================================================
// Persistent tensor-core GRU scan. h kept as bf16 hi/lo in global
// (producer-split), staged via raw cp.async. Direct counter-poll barrier.
// ======================================================================
#define GRU_SMEM_BYTES ((2 * 48 * 520 + 2 * 16 * 520) * 2 + (8 * 800) * 4)

__global__ void __launch_bounds__(256) gru_scan(const float* __restrict__ Whh,
                                                const float* __restrict__ bhh)
{
    extern __shared__ char smg[];
    bf16* Wh = (bf16*)smg;                  // [48][520]
    bf16* Wl = Wh + 48 * 520;
    bf16* Hh = Wl + 48 * 520;               // [16][520]
    bf16* Hl = Hh + 16 * 520;
    float* Red = (float*)(Hl + 16 * 520);   // [8][800] (row stride 50)

    const uint32_t WhA = cvta_smem(Wh), WlA = cvta_smem(Wl);
    const uint32_t HhA = cvta_smem(Hh), HlA = cvta_smem(Hl);

    const int tid = threadIdx.x;
    const int bg = blockIdx.x >> 5;
    const int jg = blockIdx.x & 31;
    const int b0 = bg * 16, j0 = jg * 16;

    // W slice load + hi/lo split (once)
    for (int v = tid; v < 48 * 128; v += 256) {
        int rowid = v >> 7, kc = (v & 127) << 2;
        int gate = rowid >> 4, jl = rowid & 15;
        float4 x = *(const float4*)(Whh + (long)(gate * 512 + j0 + jl) * 512 + kc);
        uint32_t h0, h1, l0, l1;
        cvt4(x, h0, h1, l0, l1);
        *(uint2*)&Wh[rowid * 520 + kc] = make_uint2(h0, h1);
        *(uint2*)&Wl[rowid * 520 + kc] = make_uint2(l0, l1);
    }

    const int warp = tid >> 5, lane = tid & 31;
    const int lr = lane >> 2;
    const int k0w = warp << 6;

    const uint32_t a_off = ((uint32_t)(lane & 15) * 520 +
                            (uint32_t)((lane >> 4) << 3)) * 2u;
    const uint32_t b_off = ((uint32_t)(((lane >> 4) << 3) + (lane & 7)) * 520 +
                            (uint32_t)(((lane >> 3) & 1) << 3)) * 2u;

    const int blc = tid >> 4, jlc = tid & 15;
    const float br = bhh[j0 + jlc];
    const float bz = bhh[512 + j0 + jlc];
    const float bnn = bhh[1024 + j0 + jlc];
    const int bglob = b0 + blc, jglob = j0 + jlc;
    const long xibase = (long)bglob * 512 * 1536 + jglob;
    volatile unsigned* barp = &g_barc[bg * 32];

    for (int t = 0; t < 512; ++t) {
        const bf16* hsh = g_hbh[t & 1];
        const bf16* hsl = g_hbl[t & 1];
        bf16* hnh = g_hbh[(t & 1) ^ 1];
        bf16* hnl = g_hbl[(t & 1) ^ 1];

        // prefetch xi (DRAM; independent of h_t)
        const long xio = xibase + (long)t * 1536;
        float xr = g_xi[xio];
        float xz = g_xi[xio + 512];
        float xn = g_xi[xio + 1024];

        // stage h tile: raw cp.async of bf16 hi/lo planes (no conversion)
#pragma unroll
        for (int i = 0; i < 4; i++) {
            int g = tid + i * 256;             // 0..1023 granules (16B each)
            int r = g >> 6, kc8 = (g & 63) << 3;
            uint32_t dst = HhA + (uint32_t)(r * 1040 + kc8 * 2);
            cp16(dst, hsh + (b0 + r) * 512 + kc8);
            cp16(dst + 16640, hsl + (b0 + r) * 512 + kc8);  // Hl plane
        }
        CP_COMMIT();
        CP_WAIT0();
        __syncthreads();

        // MMA: M=16 x N=48 x K=64 (per-warp K slice)
        float acc[6][4];
#pragma unroll
        for (int ni = 0; ni < 6; ni++)
#pragma unroll
            for (int q = 0; q < 4; q++) acc[ni][q] = 0.f;

#pragma unroll
        for (int ks = 0; ks < 4; ++ks) {
            const uint32_t kb = (uint32_t)(k0w + ks * 16) * 2u;
            uint32_t ah[4], al[4];
            ldsm_x4(HhA + a_off + kb, ah[0], ah[1], ah[2], ah[3]);
            ldsm_x4(HlA + a_off + kb, al[0], al[1], al[2], al[3]);
#pragma unroll
            for (int p = 0; p < 3; ++p) {
                uint32_t bo = b_off + (uint32_t)(p * 16 * 520) * 2u + kb;
                uint32_t bh0, bh1, bh2, bh3, bl0, bl1, bl2, bl3;
                ldsm_x4(WhA + bo, bh0, bh1, bh2, bh3);
                ldsm_x4(WlA + bo, bl0, bl1, bl2, bl3);
                mma_bf16(acc[2 * p + 0], ah, bh0, bh1);
                mma_bf16(acc[2 * p + 0], ah, bl0, bl1);
                mma_bf16(acc[2 * p + 0], al, bh0, bh1);
                mma_bf16(acc[2 * p + 1], ah, bh2, bh3);
                mma_bf16(acc[2 * p + 1], ah, bl2, bl3);
                mma_bf16(acc[2 * p + 1], al, bh2, bh3);
            }
        }

        float* rw = Red + warp * 800;
#pragma unroll
        for (int ni = 0; ni < 6; ++ni) {
            int n = ni * 8 + (lane & 3) * 2;
            *(float2*)&rw[lr * 50 + n] = make_float2(acc[ni][0], acc[ni][1]);
            *(float2*)&rw[(lr + 8) * 50 + n] = make_float2(acc[ni][2], acc[ni][3]);
        }
        __syncthreads();

        // combine: one (b,j) per thread
        float hr = br, hz = bz, hn = bnn;
#pragma unroll
        for (int w = 0; w < 8; ++w) {
            hr += Red[w * 800 + blc * 50 + jlc];
            hz += Red[w * 800 + blc * 50 + 16 + jlc];
            hn += Red[w * 800 + blc * 50 + 32 + jlc];
        }
        float hold = __bfloat162float(Hh[blc * 520 + jglob]) +
                     __bfloat162float(Hl[blc * 520 + jglob]);
        float r = __fdividef(1.f, 1.f + __expf(-(xr + hr)));
        float z = __fdividef(1.f, 1.f + __expf(-(xz + hz)));
        float e2 = __expf(2.f * (xn + r * hn));
        float n = __fdividef(e2 - 1.f, e2 + 1.f);
        float hnew = (1.f - z) * n + z * hold;

        bf16 hhi = __float2bfloat16(hnew);
        bf16 hlo = __float2bfloat16(hnew - __bfloat162float(hhi));
        long hidx = (long)bglob * 512 + jglob;
        hnh[hidx] = hhi;
        hnl[hidx] = hlo;

        // ---- per-bg barrier: monotonic counter, direct poll ----
        __syncthreads();
        if (tid == 0) {
            __threadfence();
            atomicAdd(&g_barc[bg * 32], 1u);
        }
        {   // dec hi/lo store — off the fence/arrive critical path
            long di = ((long)(bglob * 512 + t)) * 512 + jglob;
            g_dech[di] = hhi;
            g_decl[di] = hlo;
        }
        if (tid == 0) {
            unsigned want = ((unsigned)t + 1u) * 32u;
            while (*barp < want) { }
            __threadfence();
        }
        __syncthreads();
    }
}

// ======================================================================
// Softmax over S=512 per (b,t) row, mask-aware; writes attn bf16 hi/lo.
// ======================================================================
__global__ void __launch_bounds__(256) softmax_k(const float* __restrict__ sc,
                                                 const unsigned char* __restrict__ mask)
{
    const int row = blockIdx.x;
    const int b = row >> 9;
    const float* p = sc + (long)row * 512;
    const unsigned char* mp = mask + b * 512;
    const int tid = threadIdx.x;

    const float NEG_INF = -__int_as_float(0x7f800000);
    float v0 = p[tid], v1 = p[tid + 256];
    bool m0 = mp[tid] != 0, m1 = mp[tid + 256] != 0;
    if (m0) v0 = NEG_INF;
    if (m1) v1 = NEG_INF;

    __shared__ float red[8];
    __shared__ float bcast;

    float mx = fmaxf(v0, v1);
#pragma unroll
    for (int o = 16; o; o >>= 1) mx = fmaxf(mx, __shfl_xor_sync(0xffffffffu, mx, o));
    if ((tid & 31) == 0) red[tid >> 5] = mx;
    __syncthreads();
    if (tid < 8) {
        float x = red[tid];
#pragma unroll
        for (int o = 4; o; o >>= 1) x = fmaxf(x, __shfl_xor_sync(0xffu, x, o));
        if (tid == 0) bcast = x;
    }
    __syncthreads();
    mx = bcast;

    float e0 = m0 ? 0.f : __expf(v0 - mx);
    float e1 = m1 ? 0.f : __expf(v1 - mx);
    float s = e0 + e1;
#pragma unroll
    for (int o = 16; o; o >>= 1) s += __shfl_xor_sync(0xffffffffu, s, o);
    if ((tid & 31) == 0) red[tid >> 5] = s;
    __syncthreads();
    if (tid < 8) {
        float x = red[tid];
#pragma unroll
        for (int o = 4; o; o >>= 1) x += __shfl_xor_sync(0xffu, x, o);
        if (tid == 0) bcast = x;
    }
    __syncthreads();
    float inv = 1.f / bcast;
    float a0 = e0 * inv, a1 = e1 * inv;
    long base = (long)row * 512;
    bf16 h0 = __float2bfloat16(a0);
    bf16 h1 = __float2bfloat16(a1);
    g_attnh[base + tid] = h0;
    g_attnl[base + tid] = __float2bfloat16(a0 - __bfloat162float(h0));
    g_attnh[base + tid + 256] = h1;
    g_attnl[base + tid + 256] = __float2bfloat16(a1 - __bfloat162float(h1));
}

__global__ void __launch_bounds__(256) copy_h_k(float* __restrict__ dst)
{
    int i = blockIdx.x * 256 + threadIdx.x;
    if (i < 64 * 512)
        dst[i] = __bfloat162float(g_hbh[0][i]) + __bfloat162float(g_hbl[0][i]);
}

// ======================================================================
// launch
// ======================================================================
extern "C" void kernel_launch(void* const* d_in, const int* in_sizes, int n_in,
                              void* d_out, int out_size)
{
    const float* X    = (const float*)d_in[0];
    const float* Enc  = (const float*)d_in[1];
    const unsigned char* Mask = (const unsigned char*)d_in[2];
    const float* Wih  = (const float*)d_in[3];
    const float* Whh  = (const float*)d_in[4];
    const float* bih  = (const float*)d_in[5];
    const float* bhh  = (const float*)d_in[6];
    const float* Wao  = (const float*)d_in[7];
    const float* bao  = (const float*)d_in[8];
    const float* Wd   = (const float*)d_in[9];
    const float* bd   = (const float*)d_in[10];
    float* out = (float*)d_out;

    void *p_xi, *p_sc, *p_hh, *p_hl, *p_barc;
    cudaGetSymbolAddress(&p_xi, g_xi);
    cudaGetSymbolAddress(&p_sc, g_scores);
    cudaGetSymbolAddress(&p_hh, g_hbh);
    cudaGetSymbolAddress(&p_hl, g_hbl);
    cudaGetSymbolAddress(&p_barc, g_barc);
    float* xi = (float*)p_xi;
    float* sc = (float*)p_sc;

#define GET(sym) ({ void* _p; cudaGetSymbolAddress(&_p, sym); (bf16*)_p; })
    bf16 *Xh = GET(g_Xh), *Xl = GET(g_Xl);
    bf16 *Eh = GET(g_Ench), *El = GET(g_Encl);
    bf16 *Th = GET(g_ETh), *Tl = GET(g_ETl);
    bf16 *Dh = GET(g_dech), *Dl = GET(g_decl);
    bf16 *Atth = GET(g_attnh), *Attl = GET(g_attnl);
    bf16 *Mh = GET(g_mixh), *Ml = GET(g_mixl);
    bf16 *Oh = GET(g_o1h), *Ol = GET(g_o1l);
    bf16 *Wih_h = GET(g_Wihh), *Wih_l = GET(g_Wihl);
    bf16 *Wao_h = GET(g_Waoh), *Wao_l = GET(g_Waol);
    bf16 *Wd_h = GET(g_Wdh), *Wd_l = GET(g_Wdl);
#undef GET

    cudaFuncSetAttribute(gru_scan, cudaFuncAttributeMaxDynamicSharedMemorySize, GRU_SMEM_BYTES);
    cudaFuncSetAttribute(tgemm_bf<1, 0>, cudaFuncAttributeMaxDynamicSharedMemorySize, TGB_SMEM);
    cudaFuncSetAttribute(tgemm_bf<0, 0>, cudaFuncAttributeMaxDynamicSharedMemorySize, TGB_SMEM);
    cudaFuncSetAttribute(tgemm_bf<0, 1>, cudaFuncAttributeMaxDynamicSharedMemorySize, TGB_SMEM);
    cudaFuncSetAttribute(tgemm_bf<2, 1>, cudaFuncAttributeMaxDynamicSharedMemorySize, TGB_SMEM);

    // h0 = 0 (buffer 0 read at t=0); barrier counters = 0 — every launch
    cudaMemsetAsync((char*)p_hh, 0, 64 * 512 * sizeof(bf16));
    cudaMemsetAsync((char*)p_hl, 0, 64 * 512 * sizeof(bf16));
    cudaMemsetAsync(p_barc, 0, 4 * 32 * sizeof(unsigned));

    const int KBIG = 1 << 30;

    // 0) operand prep (bf16 hi/lo)
    cvt_k<<<512, 256>>>(X, Xh, Xl, (64L * 512 * 512) / 4);
    cvt_k<<<64, 256>>>(Wih, Wih_h, Wih_l, (1536L * 512) / 4);
    cvt_k<<<64, 256>>>(Wao, Wao_h, Wao_l, (512L * 1024) / 4);
    cvt_k<<<32, 256>>>(Wd, Wd_h, Wd_l, (512L * 512) / 4);
    encprep_k<<<dim3(16, 16, 64), dim3(32, 8)>>>(Enc, Eh, El, Th, Tl);

    // 1) xi = X @ Wih^T + bih : [32768,1536] fp32
    tgemm_bf<1, 0><<<dim3(12, 256, 1), 256, TGB_SMEM>>>(
        Xh, Xl, Xh, Xl, KBIG, 512, Wih_h, Wih_l, 512, bih,
        xi, nullptr, nullptr, 1536, 512, 0, 0, 0);

    // 2) GRU scan -> dec hi/lo, h_last in g_hbh/g_hbl[0]
    gru_scan<<<128, 256, GRU_SMEM_BYTES>>>(Whh, bhh);

    // 3) scores[b] = dec[b] @ enc[b]^T : fp32
    tgemm_bf<0, 0><<<dim3(4, 4, 64), 256, TGB_SMEM>>>(
        Dh, Dl, Dh, Dl, KBIG, 512, Eh, El, 512, nullptr,
        sc, nullptr, nullptr, 512, 512, 262144L, 262144L, 262144L);

    // 4) softmax (mask) -> attn hi/lo
    softmax_k<<<64 * 512, 256>>>(sc, Mask);

    // 5) mix[b] = attn[b] @ encT[b]^T : bf16 hi/lo out
    tgemm_bf<0, 1><<<dim3(4, 4, 64), 256, TGB_SMEM>>>(
        Atth, Attl, Atth, Attl, KBIG, 512, Th, Tl, 512, nullptr,
        nullptr, Mh, Ml, 512, 512, 262144L, 262144L, 262144L);

    // 6) o1 = tanh(concat(mix, dec) @ Wao^T + bao) : bf16 hi/lo out, K=1024
    tgemm_bf<2, 1><<<dim3(4, 256, 1), 256, TGB_SMEM>>>(
        Mh, Ml, Dh, Dl, 512, 512, Wao_h, Wao_l, 1024, bao,
        nullptr, Oh, Ol, 512, 1024, 0, 0, 0);

    // 7) final = o1 @ Wd^T + bd -> d_out fp32
    tgemm_bf<1, 0><<<dim3(4, 256, 1), 256, TGB_SMEM>>>(
        Oh, Ol, Oh, Ol, KBIG, 512, Wd_h, Wd_l, 512, bd,
        out, nullptr, nullptr, 512, 512, 0, 0, 0);

    // 8) h_last -> tail of d_out
    copy_h_k<<<128, 256>>>(out + (long)out_size - 64 * 512);
}